// round 14
// baseline (speedup 1.0000x reference)
#include <cuda_runtime.h>
#include <cuda_bf16.h>
#include <math.h>
#include <stdint.h>

#define DM 128
#define DB 256
#define NN 64
#define NC 100000
#define NBATCH 1024
#define CTXN 96
#define NP (NBATCH * CTXN)            // 98304 (b,c) pairs

// mma tiling
#define BM 128
#define BN 128
#define BK 64
#define ASTR 72   // BK + 8 pad (bf16 elems)
#define NTILES ((NC + BN - 1) / BN)   // 782
#define SIMS_SMEM (4 * BM * ASTR * 2) // Ah,Al,Bh,Bl = 73728 B

// encoder tiling
#define XSTR 136                      // 128 + 8 pad
#define ENCBLK 782                    // ceil(NC/128)
#define ENC_GRID (ENCBLK + NBATCH / 128)
#define ENC_SMEM ((2 * 128 * XSTR + 4 * 128 * ASTR) * 2)  // 143360 B

// topk block-max select
#define NBLKS (NC / 32)               // 3125
#define BSTR 3136
#define BCAP 128
#define TOPK_SMEM ((3136 + 4096 + 4096 + 4096 + 4096 + BCAP) * 4)  // 78592 B

// -------- scratch (device globals; no runtime allocation) --------
__device__ float g_cand_k[(size_t)NC * DM];   // 51.2 MB
__device__ float g_cand_cn[NC];
__device__ float g_xb[NBATCH * DM];
__device__ float g_kb[NBATCH * DM];
__device__ float g_sims[(size_t)NBATCH * NC]; // 409.6 MB
__device__ float g_bmax[(size_t)NBATCH * BSTR]; // 12.8 MB
__device__ int   g_tidx[NP];
__device__ float g_probs[NP];
__device__ float g_ctx[NBATCH * DM];
__device__ float g_vals[(size_t)NP * DM];                  // 50.3 MB
// bf16 hi/lo splits (batch side pre-scaled by 2)
__device__ __nv_bfloat16 g_kb_hi[NBATCH * DM];
__device__ __nv_bfloat16 g_kb_lo[NBATCH * DM];
__device__ __nv_bfloat16 g_ck_hi[(size_t)NC * DM];
__device__ __nv_bfloat16 g_ck_lo[(size_t)NC * DM];
// weight splits
__device__ __nv_bfloat16 g_wt1_hi[DB * DM], g_wt1_lo[DB * DM];
__device__ __nv_bfloat16 g_wt2_hi[DM * DB], g_wt2_lo[DM * DB];
__device__ __nv_bfloat16 g_win_hi[DM * NN], g_win_lo[DM * NN];
__device__ __nv_bfloat16 g_w1_hi[DB * DM],  g_w1_lo[DB * DM];
__device__ __nv_bfloat16 g_w2_hi[DM * DB],  g_w2_lo[DM * DB];
__device__ __nv_bfloat16 g_wk_hi[DM * DM],  g_wk_lo[DM * DM];
// T-network hidden activations
__device__ __nv_bfloat16 g_h_hi[(size_t)NP * DB];          // 50.3 MB
__device__ __nv_bfloat16 g_h_lo[(size_t)NP * DB];          // 50.3 MB

typedef unsigned long long ull;

// ---- packed f32x2 helpers (final kernel) ----
__device__ __forceinline__ void fma2(ull& d, ull a, ull b) {
    asm("fma.rn.f32x2 %0, %1, %2, %0;" : "+l"(d) : "l"(a), "l"(b));
}
__device__ __forceinline__ ull pk(float x, float y) {
    ull r; asm("mov.b64 %0, {%1, %2};" : "=l"(r) : "f"(x), "f"(y)); return r;
}
__device__ __forceinline__ float fsum2(ull v) {
    float x, y; asm("mov.b64 {%0, %1}, %2;" : "=f"(x), "=f"(y) : "l"(v)); return x + y;
}

__device__ __forceinline__ uint32_t smem_u32(const void* p) {
    uint32_t a;
    asm("{ .reg .u64 t; cvta.to.shared.u64 t, %1; cvt.u32.u64 %0, t; }"
        : "=r"(a) : "l"(p));
    return a;
}
__device__ __forceinline__ void ldsm4(uint32_t& r0, uint32_t& r1,
                                      uint32_t& r2, uint32_t& r3, uint32_t addr) {
    asm volatile("ldmatrix.sync.aligned.m8n8.x4.shared.b16 {%0,%1,%2,%3}, [%4];"
        : "=r"(r0), "=r"(r1), "=r"(r2), "=r"(r3) : "r"(addr));
}
__device__ __forceinline__ void mma16816(float* c, uint32_t a0, uint32_t a1,
                                         uint32_t a2, uint32_t a3,
                                         uint32_t b0, uint32_t b1) {
    asm volatile(
        "mma.sync.aligned.m16n8k16.row.col.f32.bf16.bf16.f32 "
        "{%0,%1,%2,%3}, {%4,%5,%6,%7}, {%8,%9}, {%0,%1,%2,%3};"
        : "+f"(c[0]), "+f"(c[1]), "+f"(c[2]), "+f"(c[3])
        : "r"(a0), "r"(a1), "r"(a2), "r"(a3), "r"(b0), "r"(b1));
}
__device__ __forceinline__ void split_bf16(float v, __nv_bfloat16& h, __nv_bfloat16& l) {
    h = __float2bfloat16(v);
    l = __float2bfloat16(v - __bfloat162float(h));
}
__device__ __forceinline__ float bf2f(__nv_bfloat16 v) { return __bfloat162float(v); }

// ============================================================
// prep: split all fp32 weights into bf16 hi/lo
// ============================================================
__global__ void __launch_bounds__(256) prep_kernel(
    const float* __restrict__ Wt1, const float* __restrict__ Wt2,
    const float* __restrict__ W_in, const float* __restrict__ W1,
    const float* __restrict__ W2, const float* __restrict__ Wk)
{
    int i = blockIdx.x * 256 + threadIdx.x;
    __nv_bfloat16 h, l;
    if (i < DB * DM) {
        split_bf16(Wt1[i], h, l); g_wt1_hi[i] = h; g_wt1_lo[i] = l;
        split_bf16(Wt2[i], h, l); g_wt2_hi[i] = h; g_wt2_lo[i] = l;
        split_bf16(W1[i],  h, l); g_w1_hi[i]  = h; g_w1_lo[i]  = l;
        split_bf16(W2[i],  h, l); g_w2_hi[i]  = h; g_w2_lo[i]  = l;
    }
    if (i < DM * NN) { split_bf16(W_in[i], h, l); g_win_hi[i] = h; g_win_lo[i] = l; }
    if (i < DM * DM) { split_bf16(Wk[i],  h, l); g_wk_hi[i]  = h; g_wk_lo[i]  = l; }
}

// ============================================================
// Tensor-core encoder (unchanged from R12)
// ============================================================
__global__ void __launch_bounds__(256) encode_tc_kernel(
    const float* __restrict__ xnum_c, const float* __restrict__ xnum_b,
    const float* __restrict__ b_in, const float* __restrict__ b1,
    const float* __restrict__ b2,
    const float* __restrict__ mg, const float* __restrict__ mb,
    const float* __restrict__ bk)
{
    extern __shared__ __nv_bfloat16 sm2[];
    __nv_bfloat16* sXh = sm2;
    __nv_bfloat16* sXl = sXh + 128 * XSTR;
    __nv_bfloat16* sAh = sXl + 128 * XSTR;
    __nv_bfloat16* sAl = sAh + 128 * ASTR;
    __nv_bfloat16* sBh = sAl + 128 * ASTR;
    __nv_bfloat16* sBl = sBh + 128 * ASTR;

    const int tid = threadIdx.x, lane = tid & 31, w = tid >> 5;
    const int wm = w & 3, wn = w >> 2;
    const bool cand = (blockIdx.x < ENCBLK);
    const int row0 = cand ? blockIdx.x * 128 : (int)(blockIdx.x - ENCBLK) * 128;
    const int nrows = cand ? min(128, NC - row0) : 128;
    const float* xnum = cand ? xnum_c : xnum_b;

    const uint32_t uXh = smem_u32(sXh), uXl = smem_u32(sXl);
    const uint32_t uAh = smem_u32(sAh), uAl = smem_u32(sAl);
    const uint32_t uBh = smem_u32(sBh), uBl = smem_u32(sBl);
    const int a_row = lane & 15, a_half = lane >> 4;
    const int b_grp = lane >> 3, b_row = lane & 7;
    const int b_nt = b_grp >> 1, b_kh = b_grp & 1;
    const int c_row = lane >> 2, c_col2 = (lane & 3) * 2;

    #pragma unroll
    for (int t = 0; t < 8; t++) {
        int idx = t * 256 + tid;
        int row = idx >> 4, q4 = (idx & 15) * 4;
        float4 v = make_float4(0.f, 0.f, 0.f, 0.f);
        if (row < nrows)
            v = *reinterpret_cast<const float4*>(&xnum[(size_t)(row0 + row) * NN + q4]);
        float vv[4] = {v.x, v.y, v.z, v.w};
        __nv_bfloat16 hh[4], ll[4];
        #pragma unroll
        for (int e = 0; e < 4; e++) split_bf16(vv[e], hh[e], ll[e]);
        *reinterpret_cast<ull*>(&sAh[row * ASTR + q4]) = *reinterpret_cast<ull*>(hh);
        *reinterpret_cast<ull*>(&sAl[row * ASTR + q4]) = *reinterpret_cast<ull*>(ll);
    }
    #pragma unroll
    for (int t = 0; t < 4; t++) {
        int idx = t * 256 + tid;
        int row = idx >> 3, c8 = (idx & 7) * 8;
        *reinterpret_cast<float4*>(&sBh[row * ASTR + c8]) =
            *reinterpret_cast<const float4*>(&g_win_hi[row * NN + c8]);
        *reinterpret_cast<float4*>(&sBl[row * ASTR + c8]) =
            *reinterpret_cast<const float4*>(&g_win_lo[row * NN + c8]);
    }
    __syncthreads();

    float c[2][8][4];
    #pragma unroll
    for (int i = 0; i < 2; i++)
        #pragma unroll
        for (int j = 0; j < 8; j++)
            #pragma unroll
            for (int q = 0; q < 4; q++) c[i][j][q] = 0.f;

    #pragma unroll
    for (int ks = 0; ks < 4; ks++) {
        const int kb = ks * 16;
        uint32_t ah[2][4], al[2][4];
        #pragma unroll
        for (int mi = 0; mi < 2; mi++) {
            uint32_t off = (uint32_t)((wm * 32 + mi * 16 + a_row) * ASTR + kb + a_half * 8) * 2;
            ldsm4(ah[mi][0], ah[mi][1], ah[mi][2], ah[mi][3], uAh + off);
            ldsm4(al[mi][0], al[mi][1], al[mi][2], al[mi][3], uAl + off);
        }
        uint32_t bh[8][2], bl[8][2];
        #pragma unroll
        for (int nq = 0; nq < 4; nq++) {
            uint32_t off = (uint32_t)((wn * 64 + nq * 16 + b_nt * 8 + b_row) * ASTR + kb + b_kh * 8) * 2;
            uint32_t r0, r1, r2, r3;
            ldsm4(r0, r1, r2, r3, uBh + off);
            bh[nq * 2][0] = r0; bh[nq * 2][1] = r1;
            bh[nq * 2 + 1][0] = r2; bh[nq * 2 + 1][1] = r3;
            ldsm4(r0, r1, r2, r3, uBl + off);
            bl[nq * 2][0] = r0; bl[nq * 2][1] = r1;
            bl[nq * 2 + 1][0] = r2; bl[nq * 2 + 1][1] = r3;
        }
        #pragma unroll
        for (int mi = 0; mi < 2; mi++)
            #pragma unroll
            for (int ni = 0; ni < 8; ni++) {
                mma16816(c[mi][ni], ah[mi][0], ah[mi][1], ah[mi][2], ah[mi][3], bh[ni][0], bh[ni][1]);
                mma16816(c[mi][ni], ah[mi][0], ah[mi][1], ah[mi][2], ah[mi][3], bl[ni][0], bl[ni][1]);
                mma16816(c[mi][ni], al[mi][0], al[mi][1], al[mi][2], al[mi][3], bh[ni][0], bh[ni][1]);
            }
    }
    #pragma unroll
    for (int mi = 0; mi < 2; mi++) {
        #pragma unroll
        for (int ni = 0; ni < 8; ni++) {
            int col = wn * 64 + ni * 8 + c_col2;
            int row = wm * 32 + mi * 16 + c_row;
            float bb0 = __ldg(&b_in[col]), bb1 = __ldg(&b_in[col + 1]);
            #pragma unroll
            for (int half = 0; half < 2; half++) {
                int r = row + half * 8;
                float x0 = c[mi][ni][half * 2]     + bb0;
                float x1 = c[mi][ni][half * 2 + 1] + bb1;
                __nv_bfloat16 h0, l0, h1, l1;
                split_bf16(x0, h0, l0); split_bf16(x1, h1, l1);
                __nv_bfloat162 ph; ph.x = h0; ph.y = h1;
                __nv_bfloat162 pl; pl.x = l0; pl.y = l1;
                *reinterpret_cast<__nv_bfloat162*>(&sXh[r * XSTR + col]) = ph;
                *reinterpret_cast<__nv_bfloat162*>(&sXl[r * XSTR + col]) = pl;
            }
        }
    }

    float c3[2][8][4];
    #pragma unroll
    for (int i = 0; i < 2; i++)
        #pragma unroll
        for (int j = 0; j < 8; j++)
            #pragma unroll
            for (int q = 0; q < 4; q++) c3[i][j][q] = 0.f;

    #pragma unroll 1
    for (int hc = 0; hc < 4; hc++) {
        __syncthreads();
        #pragma unroll
        for (int t = 0; t < 4; t++) {
            int idx = t * 256 + tid;
            int row = idx >> 4, c8 = (idx & 15) * 8;
            *reinterpret_cast<float4*>(&sBh[row * XSTR + c8]) =
                *reinterpret_cast<const float4*>(&g_w1_hi[(hc * 64 + row) * DM + c8]);
            *reinterpret_cast<float4*>(&sBl[row * XSTR + c8]) =
                *reinterpret_cast<const float4*>(&g_w1_lo[(hc * 64 + row) * DM + c8]);
        }
        __syncthreads();
        float c2[2][4][4];
        #pragma unroll
        for (int i = 0; i < 2; i++)
            #pragma unroll
            for (int j = 0; j < 4; j++)
                #pragma unroll
                for (int q = 0; q < 4; q++) c2[i][j][q] = 0.f;
        #pragma unroll
        for (int ks = 0; ks < 8; ks++) {
            const int kb = ks * 16;
            uint32_t ah[2][4], al[2][4];
            #pragma unroll
            for (int mi = 0; mi < 2; mi++) {
                uint32_t off = (uint32_t)((wm * 32 + mi * 16 + a_row) * XSTR + kb + a_half * 8) * 2;
                ldsm4(ah[mi][0], ah[mi][1], ah[mi][2], ah[mi][3], uXh + off);
                ldsm4(al[mi][0], al[mi][1], al[mi][2], al[mi][3], uXl + off);
            }
            uint32_t bh[4][2], bl[4][2];
            #pragma unroll
            for (int nq = 0; nq < 2; nq++) {
                uint32_t off = (uint32_t)((wn * 32 + nq * 16 + b_nt * 8 + b_row) * XSTR + kb + b_kh * 8) * 2;
                uint32_t r0, r1, r2, r3;
                ldsm4(r0, r1, r2, r3, uBh + off);
                bh[nq * 2][0] = r0; bh[nq * 2][1] = r1;
                bh[nq * 2 + 1][0] = r2; bh[nq * 2 + 1][1] = r3;
                ldsm4(r0, r1, r2, r3, uBl + off);
                bl[nq * 2][0] = r0; bl[nq * 2][1] = r1;
                bl[nq * 2 + 1][0] = r2; bl[nq * 2 + 1][1] = r3;
            }
            #pragma unroll
            for (int mi = 0; mi < 2; mi++)
                #pragma unroll
                for (int ni = 0; ni < 4; ni++) {
                    mma16816(c2[mi][ni], ah[mi][0], ah[mi][1], ah[mi][2], ah[mi][3], bh[ni][0], bh[ni][1]);
                    mma16816(c2[mi][ni], ah[mi][0], ah[mi][1], ah[mi][2], ah[mi][3], bl[ni][0], bl[ni][1]);
                    mma16816(c2[mi][ni], al[mi][0], al[mi][1], al[mi][2], al[mi][3], bh[ni][0], bh[ni][1]);
                }
        }
        #pragma unroll
        for (int mi = 0; mi < 2; mi++) {
            #pragma unroll
            for (int ni = 0; ni < 4; ni++) {
                int col = wn * 32 + ni * 8 + c_col2;
                int row = wm * 32 + mi * 16 + c_row;
                float bb0 = __ldg(&b1[hc * 64 + col]), bb1 = __ldg(&b1[hc * 64 + col + 1]);
                #pragma unroll
                for (int half = 0; half < 2; half++) {
                    int r = row + half * 8;
                    float h0 = fmaxf(c2[mi][ni][half * 2]     + bb0, 0.f);
                    float h1 = fmaxf(c2[mi][ni][half * 2 + 1] + bb1, 0.f);
                    __nv_bfloat16 hh0, ll0, hh1, ll1;
                    split_bf16(h0, hh0, ll0); split_bf16(h1, hh1, ll1);
                    __nv_bfloat162 ph; ph.x = hh0; ph.y = hh1;
                    __nv_bfloat162 pl; pl.x = ll0; pl.y = ll1;
                    *reinterpret_cast<__nv_bfloat162*>(&sAh[r * ASTR + col]) = ph;
                    *reinterpret_cast<__nv_bfloat162*>(&sAl[r * ASTR + col]) = pl;
                }
            }
        }
        __syncthreads();
        #pragma unroll
        for (int t = 0; t < 4; t++) {
            int idx = t * 256 + tid;
            int row = idx >> 3, c8 = (idx & 7) * 8;
            *reinterpret_cast<float4*>(&sBh[row * ASTR + c8]) =
                *reinterpret_cast<const float4*>(&g_w2_hi[row * DB + hc * 64 + c8]);
            *reinterpret_cast<float4*>(&sBl[row * ASTR + c8]) =
                *reinterpret_cast<const float4*>(&g_w2_lo[row * DB + hc * 64 + c8]);
        }
        __syncthreads();
        #pragma unroll
        for (int ks = 0; ks < 4; ks++) {
            const int kb = ks * 16;
            uint32_t ah[2][4], al[2][4];
            #pragma unroll
            for (int mi = 0; mi < 2; mi++) {
                uint32_t off = (uint32_t)((wm * 32 + mi * 16 + a_row) * ASTR + kb + a_half * 8) * 2;
                ldsm4(ah[mi][0], ah[mi][1], ah[mi][2], ah[mi][3], uAh + off);
                ldsm4(al[mi][0], al[mi][1], al[mi][2], al[mi][3], uAl + off);
            }
            uint32_t bh[8][2], bl[8][2];
            #pragma unroll
            for (int nq = 0; nq < 4; nq++) {
                uint32_t off = (uint32_t)((wn * 64 + nq * 16 + b_nt * 8 + b_row) * ASTR + kb + b_kh * 8) * 2;
                uint32_t r0, r1, r2, r3;
                ldsm4(r0, r1, r2, r3, uBh + off);
                bh[nq * 2][0] = r0; bh[nq * 2][1] = r1;
                bh[nq * 2 + 1][0] = r2; bh[nq * 2 + 1][1] = r3;
                ldsm4(r0, r1, r2, r3, uBl + off);
                bl[nq * 2][0] = r0; bl[nq * 2][1] = r1;
                bl[nq * 2 + 1][0] = r2; bl[nq * 2 + 1][1] = r3;
            }
            #pragma unroll
            for (int mi = 0; mi < 2; mi++)
                #pragma unroll
                for (int ni = 0; ni < 8; ni++) {
                    mma16816(c3[mi][ni], ah[mi][0], ah[mi][1], ah[mi][2], ah[mi][3], bh[ni][0], bh[ni][1]);
                    mma16816(c3[mi][ni], ah[mi][0], ah[mi][1], ah[mi][2], ah[mi][3], bl[ni][0], bl[ni][1]);
                    mma16816(c3[mi][ni], al[mi][0], al[mi][1], al[mi][2], al[mi][3], bh[ni][0], bh[ni][1]);
                }
        }
    }

    #pragma unroll
    for (int mi = 0; mi < 2; mi++) {
        #pragma unroll
        for (int ni = 0; ni < 8; ni++) {
            int col = wn * 64 + ni * 8 + c_col2;
            int row = wm * 32 + mi * 16 + c_row;
            float bb0 = __ldg(&b2[col]), bb1 = __ldg(&b2[col + 1]);
            #pragma unroll
            for (int half = 0; half < 2; half++) {
                int r = row + half * 8;
                __nv_bfloat162 ph = *reinterpret_cast<__nv_bfloat162*>(&sXh[r * XSTR + col]);
                __nv_bfloat162 pl = *reinterpret_cast<__nv_bfloat162*>(&sXl[r * XSTR + col]);
                float x0 = bf2f(ph.x) + bf2f(pl.x) + c3[mi][ni][half * 2]     + bb0;
                float x1 = bf2f(ph.y) + bf2f(pl.y) + c3[mi][ni][half * 2 + 1] + bb1;
                if (!cand)
                    *reinterpret_cast<float2*>(&g_xb[(size_t)(row0 + r) * DM + col]) =
                        make_float2(x0, x1);
                __nv_bfloat16 h0, l0, h1, l1;
                split_bf16(x0, h0, l0); split_bf16(x1, h1, l1);
                ph.x = h0; ph.y = h1; pl.x = l0; pl.y = l1;
                *reinterpret_cast<__nv_bfloat162*>(&sXh[r * XSTR + col]) = ph;
                *reinterpret_cast<__nv_bfloat162*>(&sXl[r * XSTR + col]) = pl;
            }
        }
    }
    __syncthreads();

    for (int r = w; r < 128; r += 8) {
        float v[4];
        #pragma unroll
        for (int i = 0; i < 4; i++) {
            int cc = lane + 32 * i;
            v[i] = bf2f(sXh[r * XSTR + cc]) + bf2f(sXl[r * XSTR + cc]);
        }
        float s = v[0] + v[1] + v[2] + v[3];
        #pragma unroll
        for (int o = 16; o; o >>= 1) s += __shfl_xor_sync(0xffffffffu, s, o);
        float mu = s * (1.f / 128.f);
        float d[4] = {v[0] - mu, v[1] - mu, v[2] - mu, v[3] - mu};
        float q = d[0] * d[0] + d[1] * d[1] + d[2] * d[2] + d[3] * d[3];
        #pragma unroll
        for (int o = 16; o; o >>= 1) q += __shfl_xor_sync(0xffffffffu, q, o);
        float rstd = rsqrtf(q * (1.f / 128.f) + 1e-5f);
        #pragma unroll
        for (int i = 0; i < 4; i++) {
            int cc = lane + 32 * i;
            float ln = d[i] * rstd * __ldg(&mg[cc]) + __ldg(&mb[cc]);
            __nv_bfloat16 h, l; split_bf16(ln, h, l);
            sXh[r * XSTR + cc] = h;
            sXl[r * XSTR + cc] = l;
        }
    }

    #pragma unroll
    for (int i = 0; i < 2; i++)
        #pragma unroll
        for (int j = 0; j < 8; j++)
            #pragma unroll
            for (int q = 0; q < 4; q++) c[i][j][q] = 0.f;
    #pragma unroll 1
    for (int kc2 = 0; kc2 < 2; kc2++) {
        __syncthreads();
        #pragma unroll
        for (int t = 0; t < 4; t++) {
            int idx = t * 256 + tid;
            int row = idx >> 3, c8 = (idx & 7) * 8;
            *reinterpret_cast<float4*>(&sBh[row * ASTR + c8]) =
                *reinterpret_cast<const float4*>(&g_wk_hi[row * DM + kc2 * 64 + c8]);
            *reinterpret_cast<float4*>(&sBl[row * ASTR + c8]) =
                *reinterpret_cast<const float4*>(&g_wk_lo[row * DM + kc2 * 64 + c8]);
        }
        __syncthreads();
        #pragma unroll
        for (int ks = 0; ks < 4; ks++) {
            const int kb = ks * 16;
            uint32_t ah[2][4], al[2][4];
            #pragma unroll
            for (int mi = 0; mi < 2; mi++) {
                uint32_t off = (uint32_t)((wm * 32 + mi * 16 + a_row) * XSTR + kc2 * 64 + kb + a_half * 8) * 2;
                ldsm4(ah[mi][0], ah[mi][1], ah[mi][2], ah[mi][3], uXh + off);
                ldsm4(al[mi][0], al[mi][1], al[mi][2], al[mi][3], uXl + off);
            }
            uint32_t bh[8][2], bl[8][2];
            #pragma unroll
            for (int nq = 0; nq < 4; nq++) {
                uint32_t off = (uint32_t)((wn * 64 + nq * 16 + b_nt * 8 + b_row) * ASTR + kb + b_kh * 8) * 2;
                uint32_t r0, r1, r2, r3;
                ldsm4(r0, r1, r2, r3, uBh + off);
                bh[nq * 2][0] = r0; bh[nq * 2][1] = r1;
                bh[nq * 2 + 1][0] = r2; bh[nq * 2 + 1][1] = r3;
                ldsm4(r0, r1, r2, r3, uBl + off);
                bl[nq * 2][0] = r0; bl[nq * 2][1] = r1;
                bl[nq * 2 + 1][0] = r2; bl[nq * 2 + 1][1] = r3;
            }
            #pragma unroll
            for (int mi = 0; mi < 2; mi++)
                #pragma unroll
                for (int ni = 0; ni < 8; ni++) {
                    mma16816(c[mi][ni], ah[mi][0], ah[mi][1], ah[mi][2], ah[mi][3], bh[ni][0], bh[ni][1]);
                    mma16816(c[mi][ni], ah[mi][0], ah[mi][1], ah[mi][2], ah[mi][3], bl[ni][0], bl[ni][1]);
                    mma16816(c[mi][ni], al[mi][0], al[mi][1], al[mi][2], al[mi][3], bh[ni][0], bh[ni][1]);
                }
        }
    }
    __syncthreads();
    #pragma unroll
    for (int mi = 0; mi < 2; mi++) {
        #pragma unroll
        for (int ni = 0; ni < 8; ni++) {
            int col = wn * 64 + ni * 8 + c_col2;
            int row = wm * 32 + mi * 16 + c_row;
            float bb0 = __ldg(&bk[col]), bb1 = __ldg(&bk[col + 1]);
            #pragma unroll
            for (int half = 0; half < 2; half++) {
                int r = row + half * 8;
                float k0 = c[mi][ni][half * 2]     + bb0;
                float k1 = c[mi][ni][half * 2 + 1] + bb1;
                __nv_bfloat16 h0, l0, h1, l1;
                split_bf16(k0, h0, l0); split_bf16(k1, h1, l1);
                __nv_bfloat162 ph; ph.x = h0; ph.y = h1;
                __nv_bfloat162 pl; pl.x = l0; pl.y = l1;
                *reinterpret_cast<__nv_bfloat162*>(&sXh[r * XSTR + col]) = ph;
                *reinterpret_cast<__nv_bfloat162*>(&sXl[r * XSTR + col]) = pl;
            }
        }
    }
    __syncthreads();

    {
        const float scale = cand ? 1.f : 2.f;
        float* out_k = cand ? g_cand_k : g_kb;
        __nv_bfloat16* out_hi = cand ? g_ck_hi : g_kb_hi;
        __nv_bfloat16* out_lo = cand ? g_ck_lo : g_kb_lo;
        #pragma unroll
        for (int t = 0; t < 16; t++) {
            int idx = t * 256 + tid;
            int row = idx >> 5, q4 = (idx & 31) * 4;
            if (row < nrows) {
                ull uh = *reinterpret_cast<ull*>(&sXh[row * XSTR + q4]);
                ull ul = *reinterpret_cast<ull*>(&sXl[row * XSTR + q4]);
                __nv_bfloat16* hp = reinterpret_cast<__nv_bfloat16*>(&uh);
                __nv_bfloat16* lp = reinterpret_cast<__nv_bfloat16*>(&ul);
                float kv[4];
                __nv_bfloat16 oh[4], ol[4];
                #pragma unroll
                for (int e = 0; e < 4; e++) {
                    kv[e] = bf2f(hp[e]) + bf2f(lp[e]);
                    split_bf16(scale * kv[e], oh[e], ol[e]);
                }
                size_t base = (size_t)(row0 + row) * DM + q4;
                *reinterpret_cast<float4*>(&out_k[base]) =
                    make_float4(kv[0], kv[1], kv[2], kv[3]);
                *reinterpret_cast<ull*>(&out_hi[base]) = *reinterpret_cast<ull*>(oh);
                *reinterpret_cast<ull*>(&out_lo[base]) = *reinterpret_cast<ull*>(ol);
            }
        }
    }
    if (cand) {
        for (int r = w; r < 128; r += 8) {
            float q = 0.f;
            #pragma unroll
            for (int i = 0; i < 4; i++) {
                int cc = lane + 32 * i;
                float v = bf2f(sXh[r * XSTR + cc]) + bf2f(sXl[r * XSTR + cc]);
                q += v * v;
            }
            #pragma unroll
            for (int o = 16; o; o >>= 1) q += __shfl_xor_sync(0xffffffffu, q, o);
            if (lane == 0 && r < nrows) g_cand_cn[row0 + r] = q;
        }
    }
}

// ============================================================
// sims via mma.sync bf16 split GEMM; epilogue also emits
// per-(row, 32-col-block) maxima into g_bmax.
// ============================================================
__global__ void __launch_bounds__(256) sims_mma_kernel()
{
    extern __shared__ __nv_bfloat16 sm[];
    __nv_bfloat16* sAh = sm;
    __nv_bfloat16* sAl = sAh + BM * ASTR;
    __nv_bfloat16* sBh = sAl + BM * ASTR;
    __nv_bfloat16* sBl = sBh + BM * ASTR;

    const int tid  = threadIdx.x;
    const int lane = tid & 31;
    const int w    = tid >> 5;
    const int wm   = w & 3;
    const int wn   = w >> 2;
    const int m0 = blockIdx.y * BM;
    const int n0 = blockIdx.x * BN;

    const uint32_t uAh = smem_u32(sAh), uAl = smem_u32(sAl);
    const uint32_t uBh = smem_u32(sBh), uBl = smem_u32(sBl);

    float c[2][8][4];
    #pragma unroll
    for (int i = 0; i < 2; i++)
        #pragma unroll
        for (int j = 0; j < 8; j++)
            #pragma unroll
            for (int q = 0; q < 4; q++) c[i][j][q] = 0.f;

    const int a_row = lane & 15, a_half = lane >> 4;
    const int b_grp = lane >> 3, b_row = lane & 7;
    const int b_nt = b_grp >> 1, b_kh = b_grp & 1;

    #pragma unroll 1
    for (int ch = 0; ch < 2; ch++) {
        const int kc = ch * BK;
        #pragma unroll
        for (int t = 0; t < 4; t++) {
            int idx = t * 256 + tid;
            int row = idx >> 3, c8 = (idx & 7) * 8;
            *reinterpret_cast<float4*>(&sAh[row * ASTR + c8]) =
                *reinterpret_cast<const float4*>(&g_kb_hi[(m0 + row) * DM + kc + c8]);
            *reinterpret_cast<float4*>(&sAl[row * ASTR + c8]) =
                *reinterpret_cast<const float4*>(&g_kb_lo[(m0 + row) * DM + kc + c8]);
        }
        #pragma unroll
        for (int t = 0; t < 4; t++) {
            int idx = t * 256 + tid;
            int row = idx >> 3, c8 = (idx & 7) * 8;
            int col = n0 + row;
            float4 vh = make_float4(0.f, 0.f, 0.f, 0.f), vl = vh;
            if (col < NC) {
                vh = *reinterpret_cast<const float4*>(&g_ck_hi[(size_t)col * DM + kc + c8]);
                vl = *reinterpret_cast<const float4*>(&g_ck_lo[(size_t)col * DM + kc + c8]);
            }
            *reinterpret_cast<float4*>(&sBh[row * ASTR + c8]) = vh;
            *reinterpret_cast<float4*>(&sBl[row * ASTR + c8]) = vl;
        }
        __syncthreads();

        #pragma unroll
        for (int ks = 0; ks < BK / 16; ks++) {
            const int kb = ks * 16;
            uint32_t ah[2][4], al[2][4];
            #pragma unroll
            for (int mi = 0; mi < 2; mi++) {
                uint32_t off = (uint32_t)((wm * 32 + mi * 16 + a_row) * ASTR + kb + a_half * 8) * 2;
                ldsm4(ah[mi][0], ah[mi][1], ah[mi][2], ah[mi][3], uAh + off);
                ldsm4(al[mi][0], al[mi][1], al[mi][2], al[mi][3], uAl + off);
            }
            uint32_t bh[8][2], bl[8][2];
            #pragma unroll
            for (int nq = 0; nq < 4; nq++) {
                uint32_t off = (uint32_t)((wn * 64 + nq * 16 + b_nt * 8 + b_row) * ASTR + kb + b_kh * 8) * 2;
                uint32_t r0, r1, r2, r3;
                ldsm4(r0, r1, r2, r3, uBh + off);
                bh[nq * 2][0] = r0; bh[nq * 2][1] = r1;
                bh[nq * 2 + 1][0] = r2; bh[nq * 2 + 1][1] = r3;
                ldsm4(r0, r1, r2, r3, uBl + off);
                bl[nq * 2][0] = r0; bl[nq * 2][1] = r1;
                bl[nq * 2 + 1][0] = r2; bl[nq * 2 + 1][1] = r3;
            }
            #pragma unroll
            for (int mi = 0; mi < 2; mi++)
                #pragma unroll
                for (int ni = 0; ni < 8; ni++) {
                    mma16816(c[mi][ni], ah[mi][0], ah[mi][1], ah[mi][2], ah[mi][3], bh[ni][0], bh[ni][1]);
                    mma16816(c[mi][ni], ah[mi][0], ah[mi][1], ah[mi][2], ah[mi][3], bl[ni][0], bl[ni][1]);
                    mma16816(c[mi][ni], al[mi][0], al[mi][1], al[mi][2], al[mi][3], bh[ni][0], bh[ni][1]);
                }
        }
        __syncthreads();
    }

    const int col_base = n0 + wn * 64 + (lane & 3) * 2;
    float2 cn[8];
    #pragma unroll
    for (int ni = 0; ni < 8; ni++) {
        int col = col_base + ni * 8;
        cn[ni].x = (col < NC) ? __ldg(&g_cand_cn[col]) : 0.f;
        cn[ni].y = (col < NC) ? __ldg(&g_cand_cn[col + 1]) : 0.f;
    }
    #pragma unroll
    for (int mi = 0; mi < 2; mi++) {
        int row = m0 + wm * 32 + mi * 16 + (lane >> 2);
        float* d0 = &g_sims[(size_t)row * NC];
        float* d1 = &g_sims[(size_t)(row + 8) * NC];
        float bmA[2] = {-3.4e38f, -3.4e38f};
        float bmB[2] = {-3.4e38f, -3.4e38f};
        #pragma unroll
        for (int ni = 0; ni < 8; ni++) {
            int col = col_base + ni * 8;
            if (col < NC) {
                float v00 = c[mi][ni][0] - cn[ni].x, v01 = c[mi][ni][1] - cn[ni].y;
                float v10 = c[mi][ni][2] - cn[ni].x, v11 = c[mi][ni][3] - cn[ni].y;
                *reinterpret_cast<float2*>(d0 + col) = make_float2(v00, v01);
                *reinterpret_cast<float2*>(d1 + col) = make_float2(v10, v11);
                int b = ni >> 2;
                bmA[b] = fmaxf(bmA[b], fmaxf(v00, v01));
                bmB[b] = fmaxf(bmB[b], fmaxf(v10, v11));
            }
        }
        #pragma unroll
        for (int b = 0; b < 2; b++) {
            float ma = bmA[b], mb2 = bmB[b];
            ma  = fmaxf(ma,  __shfl_xor_sync(0xffffffffu, ma, 1));
            ma  = fmaxf(ma,  __shfl_xor_sync(0xffffffffu, ma, 2));
            mb2 = fmaxf(mb2, __shfl_xor_sync(0xffffffffu, mb2, 1));
            mb2 = fmaxf(mb2, __shfl_xor_sync(0xffffffffu, mb2, 2));
            int cb = n0 + wn * 64 + b * 32;
            if ((lane & 3) == 0 && cb < NC) {
                int blk = cb >> 5;
                g_bmax[(size_t)row * BSTR + blk] = ma;
                g_bmax[(size_t)(row + 8) * BSTR + blk] = mb2;
            }
        }
    }
}

// ============================================================
// Block-max assisted exact top-96.
// ============================================================
__device__ __forceinline__ unsigned f2k(float f) {
    unsigned u = __float_as_uint(f);
    return (u & 0x80000000u) ? ~u : (u | 0x80000000u);
}

// exact 32-bit radix select over smem-resident keys (3 levels: 12/12/8).
// returns key T s.t. count(>T) < need <= count(>=T); *need_eq = need - count(>T)
__device__ unsigned radix_select(const unsigned* __restrict__ keys, int n, int need,
                                 unsigned* hist, unsigned* psum,
                                 int* s_bin, int* s_need, int tid, int* need_eq)
{
    // level 1: bits [31:20]
    for (int i = tid; i < 4096; i += 256) hist[i] = 0;
    __syncthreads();
    for (int i = tid; i < n; i += 256) atomicAdd(&hist[keys[i] >> 20], 1u);
    __syncthreads();
    if (tid < 128) {
        unsigned s = 0;
        for (int j = 0; j < 32; j++) s += hist[tid * 32 + j];
        psum[tid] = s;
    }
    __syncthreads();
    if (tid == 0) {
        int nd = need; unsigned cum = 0; int g = 127;
        for (; g >= 0; g--) { if (cum + psum[g] >= (unsigned)nd) break; cum += psum[g]; }
        for (int j = 31; j >= 0; j--) {
            unsigned c = hist[g * 32 + j];
            if (cum + c >= (unsigned)nd) { *s_bin = g * 32 + j; *s_need = nd - (int)cum; break; }
            cum += c;
        }
    }
    __syncthreads();
    const unsigned b1 = (unsigned)*s_bin;
    const int need1 = *s_need;
    __syncthreads();
    // level 2: bits [19:8]
    for (int i = tid; i < 4096; i += 256) hist[i] = 0;
    __syncthreads();
    for (int i = tid; i < n; i += 256) {
        unsigned k = keys[i];
        if ((k >> 20) == b1) atomicAdd(&hist[(k >> 8) & 0xFFFu], 1u);
    }
    __syncthreads();
    if (tid < 128) {
        unsigned s = 0;
        for (int j = 0; j < 32; j++) s += hist[tid * 32 + j];
        psum[tid] = s;
    }
    __syncthreads();
    if (tid == 0) {
        int nd = need1; unsigned cum = 0; int g = 127;
        for (; g >= 0; g--) { if (cum + psum[g] >= (unsigned)nd) break; cum += psum[g]; }
        for (int j = 31; j >= 0; j--) {
            unsigned c = hist[g * 32 + j];
            if (cum + c >= (unsigned)nd) { *s_bin = g * 32 + j; *s_need = nd - (int)cum; break; }
            cum += c;
        }
    }
    __syncthreads();
    const unsigned b2 = (unsigned)*s_bin;
    const int need2 = *s_need;
    const unsigned p2 = (b1 << 12) | b2;
    __syncthreads();
    // level 3: bits [7:0]
    for (int i = tid; i < 256; i += 256) hist[i] = 0;
    __syncthreads();
    for (int i = tid; i < n; i += 256) {
        unsigned k = keys[i];
        if ((k >> 8) == p2) atomicAdd(&hist[k & 0xFFu], 1u);
    }
    __syncthreads();
    if (tid == 0) {
        int nd = need2; unsigned cum = 0;
        for (int j = 255; j >= 0; j--) {
            unsigned c = hist[j];
            if (cum + c >= (unsigned)nd) { *s_bin = j; *s_need = nd - (int)cum; break; }
            cum += c;
        }
    }
    __syncthreads();
    unsigned T = (p2 << 8) | (unsigned)*s_bin;
    *need_eq = *s_need;
    __syncthreads();
    return T;
}

__global__ void __launch_bounds__(256) topk_kernel()
{
    const int row = blockIdx.x;
    const int tid = threadIdx.x;
    extern __shared__ unsigned tsm[];
    unsigned* s_keys = tsm;                      // 3136
    unsigned* hist   = s_keys + 3136;            // 4096
    float*    s_cv   = (float*)(hist + 4096);    // 4096
    int*      s_ci   = (int*)(s_cv + 4096);      // 4096
    unsigned* s_ck   = (unsigned*)(s_ci + 4096); // 4096
    int*      s_blk  = (int*)(s_ck + 4096);      // BCAP
    __shared__ unsigned psum[128];
    __shared__ int s_bin, s_need, s_nblk, s_cnt, s_eqc;
    __shared__ float s_vals[CTXN];
    __shared__ int s_ids[CTXN];
    __shared__ float s_red;

    // ---- load block-max keys
    const float* bmax = g_bmax + (size_t)row * BSTR;
    for (int i = tid; i < NBLKS; i += 256) s_keys[i] = f2k(bmax[i]);
    if (tid == 0) s_nblk = 0;
    __syncthreads();

    // ---- exact 96th-largest block max
    int dmy;
    unsigned Tb = radix_select(s_keys, NBLKS, CTXN, hist, psum, &s_bin, &s_need, tid, &dmy);

    // ---- gather candidate block ids (>= Tb). #blocks == 96 barring exact
    // fp32 blockmax ties (measure-zero for continuous data); cap at BCAP.
    for (int i = tid; i < NBLKS; i += 256) {
        if (s_keys[i] >= Tb) {
            int p = atomicAdd(&s_nblk, 1);
            if (p < BCAP) s_blk[p] = i;
        }
    }
    __syncthreads();
    const int nblk = min(s_nblk, BCAP);
    const int ncand = nblk * 32;

    // ---- gather candidate elements (coalesced 128B per block)
    const float* sims = g_sims + (size_t)row * NC;
    for (int j = tid; j < ncand; j += 256) {
        int blk = s_blk[j >> 5];
        int idx = blk * 32 + (j & 31);
        float v = sims[idx];
        s_cv[j] = v;
        s_ci[j] = idx;
        s_ck[j] = f2k(v);
    }
    if (tid == 0) { s_cnt = 0; s_eqc = 0; }
    __syncthreads();

    // ---- exact top-96 among candidates
    int need_eq;
    unsigned T = radix_select(s_ck, ncand, CTXN, hist, psum, &s_bin, &s_need, tid, &need_eq);

    for (int j = tid; j < ncand; j += 256) {
        unsigned k = s_ck[j];
        if (k > T) {
            int p = atomicAdd(&s_cnt, 1);
            s_vals[p] = s_cv[j]; s_ids[p] = s_ci[j];
        } else if (k == T) {
            int q = atomicAdd(&s_eqc, 1);
            if (q < need_eq) {
                int p = atomicAdd(&s_cnt, 1);
                s_vals[p] = s_cv[j]; s_ids[p] = s_ci[j];
            }
        }
    }
    __syncthreads();

    // ---- softmax over 96
    if (tid == 0) {
        float m = -3.4e38f;
        for (int i = 0; i < CTXN; i++) m = fmaxf(m, s_vals[i]);
        s_red = m;
    }
    __syncthreads();
    float m = s_red;
    if (tid < CTXN) s_vals[tid] = expf(s_vals[tid] - m);
    __syncthreads();
    if (tid == 0) {
        float s = 0.f;
        for (int i = 0; i < CTXN; i++) s += s_vals[i];
        s_red = 1.f / s;
    }
    __syncthreads();
    if (tid < CTXN) {
        g_probs[row * CTXN + tid] = s_vals[tid] * s_red;
        g_tidx [row * CTXN + tid] = s_ids[tid];
    }
}

// ============================================================
// ctx GEMM1 (unchanged)
// ============================================================
__global__ void __launch_bounds__(256) ctx_mma1_kernel(
    const float* __restrict__ bt1)
{
    extern __shared__ __nv_bfloat16 sm[];
    __nv_bfloat16* sAh = sm;
    __nv_bfloat16* sAl = sAh + BM * ASTR;
    __nv_bfloat16* sBh = sAl + BM * ASTR;
    __nv_bfloat16* sBl = sBh + BM * ASTR;

    const int tid  = threadIdx.x;
    const int lane = tid & 31;
    const int w    = tid >> 5;
    const int wm   = w & 3;
    const int wn   = w >> 2;
    const int m0 = blockIdx.y * BM;
    const int n0 = blockIdx.x * BN;

    const uint32_t uAh = smem_u32(sAh), uAl = smem_u32(sAl);
    const uint32_t uBh = smem_u32(sBh), uBl = smem_u32(sBl);

    float c[2][8][4];
    #pragma unroll
    for (int i = 0; i < 2; i++)
        #pragma unroll
        for (int j = 0; j < 8; j++)
            #pragma unroll
            for (int q = 0; q < 4; q++) c[i][j][q] = 0.f;

    const int a_row = lane & 15, a_half = lane >> 4;
    const int b_grp = lane >> 3, b_row = lane & 7;
    const int b_nt = b_grp >> 1, b_kh = b_grp & 1;

    #pragma unroll 1
    for (int ch = 0; ch < 2; ch++) {
        const int kc = ch * BK;
        #pragma unroll
        for (int t = 0; t < 8; t++) {
            int idx = t * 256 + tid;
            int row = idx >> 4, q4 = (idx & 15) * 4;
            int p = m0 + row;
            int b = p / CTXN;
            int ci = g_tidx[p];
            float4 kv = *reinterpret_cast<const float4*>(&g_kb[(size_t)b * DM + kc + q4]);
            float4 cv = *reinterpret_cast<const float4*>(&g_cand_k[(size_t)ci * DM + kc + q4]);
            float d[4] = {kv.x - cv.x, kv.y - cv.y, kv.z - cv.z, kv.w - cv.w};
            __nv_bfloat16 hh[4], ll[4];
            #pragma unroll
            for (int e = 0; e < 4; e++) split_bf16(d[e], hh[e], ll[e]);
            *reinterpret_cast<ull*>(&sAh[row * ASTR + q4]) = *reinterpret_cast<ull*>(hh);
            *reinterpret_cast<ull*>(&sAl[row * ASTR + q4]) = *reinterpret_cast<ull*>(ll);
        }
        #pragma unroll
        for (int t = 0; t < 4; t++) {
            int idx = t * 256 + tid;
            int row = idx >> 3, c8 = (idx & 7) * 8;
            *reinterpret_cast<float4*>(&sBh[row * ASTR + c8]) =
                *reinterpret_cast<const float4*>(&g_wt1_hi[(n0 + row) * DM + kc + c8]);
            *reinterpret_cast<float4*>(&sBl[row * ASTR + c8]) =
                *reinterpret_cast<const float4*>(&g_wt1_lo[(n0 + row) * DM + kc + c8]);
        }
        __syncthreads();

        #pragma unroll
        for (int ks = 0; ks < BK / 16; ks++) {
            const int kb = ks * 16;
            uint32_t ah[2][4], al[2][4];
            #pragma unroll
            for (int mi = 0; mi < 2; mi++) {
                uint32_t off = (uint32_t)((wm * 32 + mi * 16 + a_row) * ASTR + kb + a_half * 8) * 2;
                ldsm4(ah[mi][0], ah[mi][1], ah[mi][2], ah[mi][3], uAh + off);
                ldsm4(al[mi][0], al[mi][1], al[mi][2], al[mi][3], uAl + off);
            }
            uint32_t bh[8][2], bl[8][2];
            #pragma unroll
            for (int nq = 0; nq < 4; nq++) {
                uint32_t off = (uint32_t)((wn * 64 + nq * 16 + b_nt * 8 + b_row) * ASTR + kb + b_kh * 8) * 2;
                uint32_t r0, r1, r2, r3;
                ldsm4(r0, r1, r2, r3, uBh + off);
                bh[nq * 2][0] = r0; bh[nq * 2][1] = r1;
                bh[nq * 2 + 1][0] = r2; bh[nq * 2 + 1][1] = r3;
                ldsm4(r0, r1, r2, r3, uBl + off);
                bl[nq * 2][0] = r0; bl[nq * 2][1] = r1;
                bl[nq * 2 + 1][0] = r2; bl[nq * 2 + 1][1] = r3;
            }
            #pragma unroll
            for (int mi = 0; mi < 2; mi++)
                #pragma unroll
                for (int ni = 0; ni < 8; ni++) {
                    mma16816(c[mi][ni], ah[mi][0], ah[mi][1], ah[mi][2], ah[mi][3], bh[ni][0], bh[ni][1]);
                    mma16816(c[mi][ni], ah[mi][0], ah[mi][1], ah[mi][2], ah[mi][3], bl[ni][0], bl[ni][1]);
                    mma16816(c[mi][ni], al[mi][0], al[mi][1], al[mi][2], al[mi][3], bh[ni][0], bh[ni][1]);
                }
        }
        __syncthreads();
    }

    const int col_base = n0 + wn * 64 + (lane & 3) * 2;
    #pragma unroll
    for (int mi = 0; mi < 2; mi++) {
        int row = m0 + wm * 32 + mi * 16 + (lane >> 2);
        #pragma unroll
        for (int ni = 0; ni < 8; ni++) {
            int col = col_base + ni * 8;
            float b0 = __ldg(&bt1[col]), b1v = __ldg(&bt1[col + 1]);
            float h00 = fmaxf(c[mi][ni][0] + b0, 0.f);
            float h01 = fmaxf(c[mi][ni][1] + b1v, 0.f);
            float h10 = fmaxf(c[mi][ni][2] + b0, 0.f);
            float h11 = fmaxf(c[mi][ni][3] + b1v, 0.f);
            __nv_bfloat16 h, l;
            __nv_bfloat162 ph, pl;
            split_bf16(h00, h, l); ph.x = h; pl.x = l;
            split_bf16(h01, h, l); ph.y = h; pl.y = l;
            *reinterpret_cast<__nv_bfloat162*>(&g_h_hi[(size_t)row * DB + col]) = ph;
            *reinterpret_cast<__nv_bfloat162*>(&g_h_lo[(size_t)row * DB + col]) = pl;
            split_bf16(h10, h, l); ph.x = h; pl.x = l;
            split_bf16(h11, h, l); ph.y = h; pl.y = l;
            *reinterpret_cast<__nv_bfloat162*>(&g_h_hi[(size_t)(row + 8) * DB + col]) = ph;
            *reinterpret_cast<__nv_bfloat162*>(&g_h_lo[(size_t)(row + 8) * DB + col]) = pl;
        }
    }
}

// ============================================================
// ctx GEMM2 (unchanged)
// ============================================================
__global__ void __launch_bounds__(256) ctx_mma2_kernel(
    const float* __restrict__ cand_y,
    const float* __restrict__ w_le, const float* __restrict__ b_le)
{
    extern __shared__ __nv_bfloat16 sm[];
    __nv_bfloat16* sAh = sm;
    __nv_bfloat16* sAl = sAh + BM * ASTR;
    __nv_bfloat16* sBh = sAl + BM * ASTR;
    __nv_bfloat16* sBl = sBh + BM * ASTR;

    const int tid  = threadIdx.x;
    const int lane = tid & 31;
    const int w    = tid >> 5;
    const int wm   = w & 3;
    const int wn   = w >> 2;
    const int m0 = blockIdx.y * BM;

    const uint32_t uAh = smem_u32(sAh), uAl = smem_u32(sAl);
    const uint32_t uBh = smem_u32(sBh), uBl = smem_u32(sBl);

    float c[2][8][4];
    #pragma unroll
    for (int i = 0; i < 2; i++)
        #pragma unroll
        for (int j = 0; j < 8; j++)
            #pragma unroll
            for (int q = 0; q < 4; q++) c[i][j][q] = 0.f;

    const int a_row = lane & 15, a_half = lane >> 4;
    const int b_grp = lane >> 3, b_row = lane & 7;
    const int b_nt = b_grp >> 1, b_kh = b_grp & 1;

    #pragma unroll 1
    for (int ch = 0; ch < 4; ch++) {
        const int kc = ch * BK;
        #pragma unroll
        for (int t = 0; t < 4; t++) {
            int idx = t * 256 + tid;
            int row = idx >> 3, c8 = (idx & 7) * 8;
            *reinterpret_cast<float4*>(&sAh[row * ASTR + c8]) =
                *reinterpret_cast<const float4*>(&g_h_hi[(size_t)(m0 + row) * DB + kc + c8]);
            *reinterpret_cast<float4*>(&sAl[row * ASTR + c8]) =
                *reinterpret_cast<const float4*>(&g_h_lo[(size_t)(m0 + row) * DB + kc + c8]);
        }
        #pragma unroll
        for (int t = 0; t < 4; t++) {
            int idx = t * 256 + tid;
            int row = idx >> 3, c8 = (idx & 7) * 8;
            *reinterpret_cast<float4*>(&sBh[row * ASTR + c8]) =
                *reinterpret_cast<const float4*>(&g_wt2_hi[row * DB + kc + c8]);
            *reinterpret_cast<float4*>(&sBl[row * ASTR + c8]) =
                *reinterpret_cast<const float4*>(&g_wt2_lo[row * DB + kc + c8]);
        }
        __syncthreads();

        #pragma unroll
        for (int ks = 0; ks < BK / 16; ks++) {
            const int kb = ks * 16;
            uint32_t ah[2][4], al[2][4];
            #pragma unroll
            for (int mi = 0; mi < 2; mi++) {
                uint32_t off = (uint32_t)((wm * 32 + mi * 16 + a_row) * ASTR + kb + a_half * 8) * 2;
                ldsm4(ah[mi][0], ah[mi][1], ah[mi][2], ah[mi][3], uAh + off);
                ldsm4(al[mi][0], al[mi][1], al[mi][2], al[mi][3], uAl + off);
            }
            uint32_t bh[8][2], bl[8][2];
            #pragma unroll
            for (int nq = 0; nq < 4; nq++) {
                uint32_t off = (uint32_t)((wn * 64 + nq * 16 + b_nt * 8 + b_row) * ASTR + kb + b_kh * 8) * 2;
                uint32_t r0, r1, r2, r3;
                ldsm4(r0, r1, r2, r3, uBh + off);
                bh[nq * 2][0] = r0; bh[nq * 2][1] = r1;
                bh[nq * 2 + 1][0] = r2; bh[nq * 2 + 1][1] = r3;
                ldsm4(r0, r1, r2, r3, uBl + off);
                bl[nq * 2][0] = r0; bl[nq * 2][1] = r1;
                bl[nq * 2 + 1][0] = r2; bl[nq * 2 + 1][1] = r3;
            }
            #pragma unroll
            for (int mi = 0; mi < 2; mi++)
                #pragma unroll
                for (int ni = 0; ni < 8; ni++) {
                    mma16816(c[mi][ni], ah[mi][0], ah[mi][1], ah[mi][2], ah[mi][3], bh[ni][0], bh[ni][1]);
                    mma16816(c[mi][ni], ah[mi][0], ah[mi][1], ah[mi][2], ah[mi][3], bl[ni][0], bl[ni][1]);
                    mma16816(c[mi][ni], al[mi][0], al[mi][1], al[mi][2], al[mi][3], bh[ni][0], bh[ni][1]);
                }
        }
        __syncthreads();
    }

    float* s_prob = reinterpret_cast<float*>(sm);
    float* s_y    = s_prob + BM;
    float* s_wle  = s_y + BM;
    float* s_ble  = s_wle + DM;
    if (tid < BM) {
        int p = m0 + tid;
        s_prob[tid] = g_probs[p];
        s_y[tid]    = __ldg(&cand_y[g_tidx[p]]);
    } else if (tid < BM + DM) {
        int j = tid - BM;
        s_wle[j] = __ldg(&w_le[j]);
        s_ble[j] = __ldg(&b_le[j]);
    }
    __syncthreads();

    const int col_base = wn * 64 + (lane & 3) * 2;
    #pragma unroll
    for (int mi = 0; mi < 2; mi++) {
        int r0 = wm * 32 + mi * 16 + (lane >> 2);
        int r1 = r0 + 8;
        float p0 = s_prob[r0], y0 = s_y[r0];
        float p1 = s_prob[r1], y1 = s_y[r1];
        #pragma unroll
        for (int ni = 0; ni < 8; ni++) {
            int col = col_base + ni * 8;
            float wl0 = s_wle[col], wl1 = s_wle[col + 1];
            float bl0 = s_ble[col], bl1 = s_ble[col + 1];
            *reinterpret_cast<float2*>(&g_vals[(size_t)(m0 + r0) * DM + col]) =
                make_float2(p0 * (y0 * wl0 + bl0 + c[mi][ni][0]),
                            p0 * (y0 * wl1 + bl1 + c[mi][ni][1]));
            *reinterpret_cast<float2*>(&g_vals[(size_t)(m0 + r1) * DM + col]) =
                make_float2(p1 * (y1 * wl0 + bl0 + c[mi][ni][2]),
                            p1 * (y1 * wl1 + bl1 + c[mi][ni][3]));
        }
    }
}

// Context reduce (unchanged)
__global__ void __launch_bounds__(128) ctx_reduce_kernel()
{
    const int b = blockIdx.x;
    const int j = threadIdx.x;
    const float* v = g_vals + (size_t)b * CTXN * DM + j;
    float s = 0.f;
    #pragma unroll 8
    for (int c = 0; c < CTXN; c++) s += v[(size_t)c * DM];
    g_ctx[(size_t)b * DM + j] = s;
}

// ============================================================
// Final (unchanged)
// ============================================================
__global__ void __launch_bounds__(128) final_kernel(
    const float* __restrict__ pg, const float* __restrict__ pb,
    const float* __restrict__ pW1, const float* __restrict__ pb1,
    const float* __restrict__ pW2, const float* __restrict__ pb2,
    const float* __restrict__ hg, const float* __restrict__ hb,
    const float* __restrict__ Wh, const float* __restrict__ bh,
    float* __restrict__ out)
{
    __shared__ float s_x[16][DM];
    __shared__ float s_ln[16][DM];
    __shared__ float s_h[16][DB];
    const int tid = threadIdx.x, lane = tid & 31, wid = tid >> 5;
    const int row0 = blockIdx.x * 16;

    #pragma unroll
    for (int r = 0; r < 16; r++)
        s_x[r][tid] = g_xb[(size_t)(row0 + r) * DM + tid]
                    + g_ctx[(size_t)(row0 + r) * DM + tid];
    __syncthreads();
    for (int r = wid; r < 16; r += 4) {
        float v0 = s_x[r][lane], v1 = s_x[r][lane + 32],
              v2 = s_x[r][lane + 64], v3 = s_x[r][lane + 96];
        float s = v0 + v1 + v2 + v3;
        #pragma unroll
        for (int o = 16; o; o >>= 1) s += __shfl_xor_sync(0xffffffffu, s, o);
        float mu = s * (1.f / 128.f);
        float d0 = v0 - mu, d1 = v1 - mu, d2 = v2 - mu, d3 = v3 - mu;
        float q = d0 * d0 + d1 * d1 + d2 * d2 + d3 * d3;
        #pragma unroll
        for (int o = 16; o; o >>= 1) q += __shfl_xor_sync(0xffffffffu, q, o);
        float rstd = rsqrtf(q * (1.f / 128.f) + 1e-5f);
        s_ln[r][lane]      = d0 * rstd * __ldg(&pg[lane])      + __ldg(&pb[lane]);
        s_ln[r][lane + 32] = d1 * rstd * __ldg(&pg[lane + 32]) + __ldg(&pb[lane + 32]);
        s_ln[r][lane + 64] = d2 * rstd * __ldg(&pg[lane + 64]) + __ldg(&pb[lane + 64]);
        s_ln[r][lane + 96] = d3 * rstd * __ldg(&pg[lane + 96]) + __ldg(&pb[lane + 96]);
    }
    __syncthreads();
    {
        ull a0[16], a1[16];
        float bb0 = __ldg(&pb1[tid]), bb1 = __ldg(&pb1[tid + 128]);
        #pragma unroll
        for (int r = 0; r < 16; r++) { a0[r] = pk(bb0, 0.f); a1[r] = pk(bb1, 0.f); }
        const ulonglong2* w40 = reinterpret_cast<const ulonglong2*>(pW1 + tid * DM);
        const ulonglong2* w41 = reinterpret_cast<const ulonglong2*>(pW1 + (tid + 128) * DM);
        #pragma unroll 4
        for (int jj = 0; jj < DM / 4; jj++) {
            ulonglong2 w0 = w40[jj], w1 = w41[jj];
            #pragma unroll
            for (int r = 0; r < 16; r++) {
                ulonglong2 s = *reinterpret_cast<const ulonglong2*>(&s_ln[r][jj * 4]);
                fma2(a0[r], w0.x, s.x); fma2(a0[r], w0.y, s.y);
                fma2(a1[r], w1.x, s.x); fma2(a1[r], w1.y, s.y);
            }
        }
        #pragma unroll
        for (int r = 0; r < 16; r++) {
            s_h[r][tid]       = fmaxf(fsum2(a0[r]), 0.f);
            s_h[r][tid + 128] = fmaxf(fsum2(a1[r]), 0.f);
        }
    }
    __syncthreads();
    {
        ull acc[16];
        float b2v = __ldg(&pb2[tid]);
        #pragma unroll
        for (int r = 0; r < 16; r++) acc[r] = pk(b2v, 0.f);
        const ulonglong2* w4 = reinterpret_cast<const ulonglong2*>(pW2 + tid * DB);
        #pragma unroll 2
        for (int jj = 0; jj < DB / 4; jj++) {
            ulonglong2 w = w4[jj];
            #pragma unroll
            for (int r = 0; r < 16; r++) {
                ulonglong2 s = *reinterpret_cast<const ulonglong2*>(&s_h[r][jj * 4]);
                fma2(acc[r], w.x, s.x); fma2(acc[r], w.y, s.y);
            }
        }
        #pragma unroll
        for (int r = 0; r < 16; r++) s_x[r][tid] += fsum2(acc[r]);
    }
    __syncthreads();
    for (int r = wid; r < 16; r += 4) {
        float v0 = s_x[r][lane], v1 = s_x[r][lane + 32],
              v2 = s_x[r][lane + 64], v3 = s_x[r][lane + 96];
        float s = v0 + v1 + v2 + v3;
        #pragma unroll
        for (int o = 16; o; o >>= 1) s += __shfl_xor_sync(0xffffffffu, s, o);
        float mu = s * (1.f / 128.f);
        float d0 = v0 - mu, d1 = v1 - mu, d2 = v2 - mu, d3 = v3 - mu;
        float q = d0 * d0 + d1 * d1 + d2 * d2 + d3 * d3;
        #pragma unroll
        for (int o = 16; o; o >>= 1) q += __shfl_xor_sync(0xffffffffu, q, o);
        float rstd = rsqrtf(q * (1.f / 128.f) + 1e-5f);
        s_ln[r][lane]      = fmaxf(d0 * rstd * __ldg(&hg[lane])      + __ldg(&hb[lane]), 0.f);
        s_ln[r][lane + 32] = fmaxf(d1 * rstd * __ldg(&hg[lane + 32]) + __ldg(&hb[lane + 32]), 0.f);
        s_ln[r][lane + 64] = fmaxf(d2 * rstd * __ldg(&hg[lane + 64]) + __ldg(&hb[lane + 64]), 0.f);
        s_ln[r][lane + 96] = fmaxf(d3 * rstd * __ldg(&hg[lane + 96]) + __ldg(&hb[lane + 96]), 0.f);
    }
    __syncthreads();
    for (int r = wid; r < 16; r += 4) {
        float p0 = 0.f, p1 = 0.f;
        #pragma unroll
        for (int q = 0; q < 4; q++) {
            float v = s_ln[r][lane + 32 * q];
            p0 += v * __ldg(&Wh[lane + 32 * q]);
            p1 += v * __ldg(&Wh[128 + lane + 32 * q]);
        }
        #pragma unroll
        for (int o = 16; o; o >>= 1) {
            p0 += __shfl_xor_sync(0xffffffffu, p0, o);
            p1 += __shfl_xor_sync(0xffffffffu, p1, o);
        }
        if (lane == 0) {
            out[(row0 + r) * 2 + 0] = p0 + __ldg(&bh[0]);
            out[(row0 + r) * 2 + 1] = p1 + __ldg(&bh[1]);
        }
    }
}

// ============================================================
extern "C" void kernel_launch(void* const* d_in, const int* in_sizes, int n_in,
                              void* d_out, int out_size)
{
    const float* x_num  = (const float*)d_in[0];
    const float* cand_x = (const float*)d_in[1];
    const float* cand_y = (const float*)d_in[2];
    const float* W_in   = (const float*)d_in[3];
    const float* b_in   = (const float*)d_in[4];
    const float* eW1    = (const float*)d_in[5];
    const float* eb1    = (const float*)d_in[6];
    const float* eW2    = (const float*)d_in[7];
    const float* eb2    = (const float*)d_in[8];
    const float* mg     = (const float*)d_in[9];
    const float* mb     = (const float*)d_in[10];
    const float* Wk     = (const float*)d_in[11];
    const float* bk     = (const float*)d_in[12];
    const float* w_le   = (const float*)d_in[13];
    const float* b_le   = (const float*)d_in[14];
    const float* Wt1    = (const float*)d_in[15];
    const float* bt1    = (const float*)d_in[16];
    const float* Wt2    = (const float*)d_in[17];
    const float* pg     = (const float*)d_in[18];
    const float* pb     = (const float*)d_in[19];
    const float* pW1    = (const float*)d_in[20];
    const float* pb1    = (const float*)d_in[21];
    const float* pW2    = (const float*)d_in[22];
    const float* pb2    = (const float*)d_in[23];
    const float* hg     = (const float*)d_in[24];
    const float* hb     = (const float*)d_in[25];
    const float* Wh     = (const float*)d_in[26];
    const float* bh     = (const float*)d_in[27];
    float* out = (float*)d_out;

    cudaFuncSetAttribute(encode_tc_kernel,
                         cudaFuncAttributeMaxDynamicSharedMemorySize, ENC_SMEM);
    cudaFuncSetAttribute(sims_mma_kernel,
                         cudaFuncAttributeMaxDynamicSharedMemorySize, SIMS_SMEM);
    cudaFuncSetAttribute(topk_kernel,
                         cudaFuncAttributeMaxDynamicSharedMemorySize, TOPK_SMEM);
    cudaFuncSetAttribute(ctx_mma1_kernel,
                         cudaFuncAttributeMaxDynamicSharedMemorySize, SIMS_SMEM);
    cudaFuncSetAttribute(ctx_mma2_kernel,
                         cudaFuncAttributeMaxDynamicSharedMemorySize, SIMS_SMEM);

    prep_kernel<<<(DB * DM + 255) / 256, 256>>>(Wt1, Wt2, W_in, eW1, eW2, Wk);
    encode_tc_kernel<<<ENC_GRID, 256, ENC_SMEM>>>(cand_x, x_num,
        b_in, eb1, eb2, mg, mb, bk);
    sims_mma_kernel<<<dim3(NTILES, NBATCH / BM), 256, SIMS_SMEM>>>();
    topk_kernel<<<NBATCH, 256, TOPK_SMEM>>>();
    ctx_mma1_kernel<<<dim3(DB / BN, NP / BM), 256, SIMS_SMEM>>>(bt1);
    ctx_mma2_kernel<<<dim3(1, NP / BM), 256, SIMS_SMEM>>>(cand_y, w_le, b_le);
    ctx_reduce_kernel<<<NBATCH, 128>>>();
    final_kernel<<<NBATCH / 16, 128>>>(pg, pb, pW1, pb1, pW2, pb2, hg, hb, Wh, bh, out);
}

// round 15
// speedup vs baseline: 1.0040x; 1.0040x over previous
#include <cuda_runtime.h>
#include <cuda_bf16.h>
#include <math.h>
#include <stdint.h>

#define DM 128
#define DB 256
#define NN 64
#define NC 100000
#define NBATCH 1024
#define CTXN 96
#define NP (NBATCH * CTXN)            // 98304 (b,c) pairs

// mma tiling
#define BM 128
#define BN 128
#define BK 64
#define ASTR 72   // BK + 8 pad (bf16 elems)
#define NTILES ((NC + BN - 1) / BN)   // 782
#define SIMS_SMEM (4 * BM * ASTR * 2) // Ah,Al,Bh,Bl = 73728 B

// encoder tiling
#define XSTR 136                      // 128 + 8 pad
#define ENCBLK 782                    // ceil(NC/128)
#define ENC_GRID (ENCBLK + NBATCH / 128)
#define ENC_SMEM ((2 * 128 * XSTR + 4 * 128 * ASTR) * 2)  // 143360 B

// topk block-max select
#define NBLKS (NC / 32)               // 3125
#define BSTR 3136
#define BCAP 128
#define TOPK_SMEM ((3136 + 4096 + 4096 + 4096 + 4096 + BCAP) * 4)  // 78592 B

// -------- scratch (device globals; no runtime allocation) --------
__device__ float g_cand_k[(size_t)NC * DM];   // 51.2 MB
__device__ float g_cand_cn[NC];
__device__ float g_xb[NBATCH * DM];
__device__ float g_kb[NBATCH * DM];
__device__ float g_sims[(size_t)NBATCH * NC]; // 409.6 MB
__device__ float g_bmax[(size_t)NBATCH * BSTR]; // 12.8 MB
__device__ int   g_tidx[NP];
__device__ float g_probs[NP];
__device__ float g_ctx[NBATCH * DM];
__device__ float g_vals[(size_t)NP * DM];                  // 50.3 MB
// bf16 hi/lo splits (batch side pre-scaled by 2)
__device__ __nv_bfloat16 g_kb_hi[NBATCH * DM];
__device__ __nv_bfloat16 g_kb_lo[NBATCH * DM];
__device__ __nv_bfloat16 g_ck_hi[(size_t)NC * DM];
__device__ __nv_bfloat16 g_ck_lo[(size_t)NC * DM];
// weight splits
__device__ __nv_bfloat16 g_wt1_hi[DB * DM], g_wt1_lo[DB * DM];
__device__ __nv_bfloat16 g_wt2_hi[DM * DB], g_wt2_lo[DM * DB];
__device__ __nv_bfloat16 g_win_hi[DM * NN], g_win_lo[DM * NN];
__device__ __nv_bfloat16 g_w1_hi[DB * DM],  g_w1_lo[DB * DM];
__device__ __nv_bfloat16 g_w2_hi[DM * DB],  g_w2_lo[DM * DB];
__device__ __nv_bfloat16 g_wk_hi[DM * DM],  g_wk_lo[DM * DM];
// T-network hidden activations
__device__ __nv_bfloat16 g_h_hi[(size_t)NP * DB];          // 50.3 MB
__device__ __nv_bfloat16 g_h_lo[(size_t)NP * DB];          // 50.3 MB

typedef unsigned long long ull;

// ---- packed f32x2 helpers (final kernel) ----
__device__ __forceinline__ void fma2(ull& d, ull a, ull b) {
    asm("fma.rn.f32x2 %0, %1, %2, %0;" : "+l"(d) : "l"(a), "l"(b));
}
__device__ __forceinline__ ull pk(float x, float y) {
    ull r; asm("mov.b64 %0, {%1, %2};" : "=l"(r) : "f"(x), "f"(y)); return r;
}
__device__ __forceinline__ float fsum2(ull v) {
    float x, y; asm("mov.b64 {%0, %1}, %2;" : "=f"(x), "=f"(y) : "l"(v)); return x + y;
}

__device__ __forceinline__ uint32_t smem_u32(const void* p) {
    uint32_t a;
    asm("{ .reg .u64 t; cvta.to.shared.u64 t, %1; cvt.u32.u64 %0, t; }"
        : "=r"(a) : "l"(p));
    return a;
}
__device__ __forceinline__ void ldsm4(uint32_t& r0, uint32_t& r1,
                                      uint32_t& r2, uint32_t& r3, uint32_t addr) {
    asm volatile("ldmatrix.sync.aligned.m8n8.x4.shared.b16 {%0,%1,%2,%3}, [%4];"
        : "=r"(r0), "=r"(r1), "=r"(r2), "=r"(r3) : "r"(addr));
}
__device__ __forceinline__ void mma16816(float* c, uint32_t a0, uint32_t a1,
                                         uint32_t a2, uint32_t a3,
                                         uint32_t b0, uint32_t b1) {
    asm volatile(
        "mma.sync.aligned.m16n8k16.row.col.f32.bf16.bf16.f32 "
        "{%0,%1,%2,%3}, {%4,%5,%6,%7}, {%8,%9}, {%0,%1,%2,%3};"
        : "+f"(c[0]), "+f"(c[1]), "+f"(c[2]), "+f"(c[3])
        : "r"(a0), "r"(a1), "r"(a2), "r"(a3), "r"(b0), "r"(b1));
}
__device__ __forceinline__ void split_bf16(float v, __nv_bfloat16& h, __nv_bfloat16& l) {
    h = __float2bfloat16(v);
    l = __float2bfloat16(v - __bfloat162float(h));
}
__device__ __forceinline__ float bf2f(__nv_bfloat16 v) { return __bfloat162float(v); }

// ============================================================
// prep: split all fp32 weights into bf16 hi/lo
// ============================================================
__global__ void __launch_bounds__(256) prep_kernel(
    const float* __restrict__ Wt1, const float* __restrict__ Wt2,
    const float* __restrict__ W_in, const float* __restrict__ W1,
    const float* __restrict__ W2, const float* __restrict__ Wk)
{
    int i = blockIdx.x * 256 + threadIdx.x;
    __nv_bfloat16 h, l;
    if (i < DB * DM) {
        split_bf16(Wt1[i], h, l); g_wt1_hi[i] = h; g_wt1_lo[i] = l;
        split_bf16(Wt2[i], h, l); g_wt2_hi[i] = h; g_wt2_lo[i] = l;
        split_bf16(W1[i],  h, l); g_w1_hi[i]  = h; g_w1_lo[i]  = l;
        split_bf16(W2[i],  h, l); g_w2_hi[i]  = h; g_w2_lo[i]  = l;
    }
    if (i < DM * NN) { split_bf16(W_in[i], h, l); g_win_hi[i] = h; g_win_lo[i] = l; }
    if (i < DM * DM) { split_bf16(Wk[i],  h, l); g_wk_hi[i]  = h; g_wk_lo[i]  = l; }
}

// ============================================================
// Tensor-core encoder (unchanged from R12)
// ============================================================
__global__ void __launch_bounds__(256) encode_tc_kernel(
    const float* __restrict__ xnum_c, const float* __restrict__ xnum_b,
    const float* __restrict__ b_in, const float* __restrict__ b1,
    const float* __restrict__ b2,
    const float* __restrict__ mg, const float* __restrict__ mb,
    const float* __restrict__ bk)
{
    extern __shared__ __nv_bfloat16 sm2[];
    __nv_bfloat16* sXh = sm2;
    __nv_bfloat16* sXl = sXh + 128 * XSTR;
    __nv_bfloat16* sAh = sXl + 128 * XSTR;
    __nv_bfloat16* sAl = sAh + 128 * ASTR;
    __nv_bfloat16* sBh = sAl + 128 * ASTR;
    __nv_bfloat16* sBl = sBh + 128 * ASTR;

    const int tid = threadIdx.x, lane = tid & 31, w = tid >> 5;
    const int wm = w & 3, wn = w >> 2;
    const bool cand = (blockIdx.x < ENCBLK);
    const int row0 = cand ? blockIdx.x * 128 : (int)(blockIdx.x - ENCBLK) * 128;
    const int nrows = cand ? min(128, NC - row0) : 128;
    const float* xnum = cand ? xnum_c : xnum_b;

    const uint32_t uXh = smem_u32(sXh), uXl = smem_u32(sXl);
    const uint32_t uAh = smem_u32(sAh), uAl = smem_u32(sAl);
    const uint32_t uBh = smem_u32(sBh), uBl = smem_u32(sBl);
    const int a_row = lane & 15, a_half = lane >> 4;
    const int b_grp = lane >> 3, b_row = lane & 7;
    const int b_nt = b_grp >> 1, b_kh = b_grp & 1;
    const int c_row = lane >> 2, c_col2 = (lane & 3) * 2;

    #pragma unroll
    for (int t = 0; t < 8; t++) {
        int idx = t * 256 + tid;
        int row = idx >> 4, q4 = (idx & 15) * 4;
        float4 v = make_float4(0.f, 0.f, 0.f, 0.f);
        if (row < nrows)
            v = *reinterpret_cast<const float4*>(&xnum[(size_t)(row0 + row) * NN + q4]);
        float vv[4] = {v.x, v.y, v.z, v.w};
        __nv_bfloat16 hh[4], ll[4];
        #pragma unroll
        for (int e = 0; e < 4; e++) split_bf16(vv[e], hh[e], ll[e]);
        *reinterpret_cast<ull*>(&sAh[row * ASTR + q4]) = *reinterpret_cast<ull*>(hh);
        *reinterpret_cast<ull*>(&sAl[row * ASTR + q4]) = *reinterpret_cast<ull*>(ll);
    }
    #pragma unroll
    for (int t = 0; t < 4; t++) {
        int idx = t * 256 + tid;
        int row = idx >> 3, c8 = (idx & 7) * 8;
        *reinterpret_cast<float4*>(&sBh[row * ASTR + c8]) =
            *reinterpret_cast<const float4*>(&g_win_hi[row * NN + c8]);
        *reinterpret_cast<float4*>(&sBl[row * ASTR + c8]) =
            *reinterpret_cast<const float4*>(&g_win_lo[row * NN + c8]);
    }
    __syncthreads();

    float c[2][8][4];
    #pragma unroll
    for (int i = 0; i < 2; i++)
        #pragma unroll
        for (int j = 0; j < 8; j++)
            #pragma unroll
            for (int q = 0; q < 4; q++) c[i][j][q] = 0.f;

    #pragma unroll
    for (int ks = 0; ks < 4; ks++) {
        const int kb = ks * 16;
        uint32_t ah[2][4], al[2][4];
        #pragma unroll
        for (int mi = 0; mi < 2; mi++) {
            uint32_t off = (uint32_t)((wm * 32 + mi * 16 + a_row) * ASTR + kb + a_half * 8) * 2;
            ldsm4(ah[mi][0], ah[mi][1], ah[mi][2], ah[mi][3], uAh + off);
            ldsm4(al[mi][0], al[mi][1], al[mi][2], al[mi][3], uAl + off);
        }
        uint32_t bh[8][2], bl[8][2];
        #pragma unroll
        for (int nq = 0; nq < 4; nq++) {
            uint32_t off = (uint32_t)((wn * 64 + nq * 16 + b_nt * 8 + b_row) * ASTR + kb + b_kh * 8) * 2;
            uint32_t r0, r1, r2, r3;
            ldsm4(r0, r1, r2, r3, uBh + off);
            bh[nq * 2][0] = r0; bh[nq * 2][1] = r1;
            bh[nq * 2 + 1][0] = r2; bh[nq * 2 + 1][1] = r3;
            ldsm4(r0, r1, r2, r3, uBl + off);
            bl[nq * 2][0] = r0; bl[nq * 2][1] = r1;
            bl[nq * 2 + 1][0] = r2; bl[nq * 2 + 1][1] = r3;
        }
        #pragma unroll
        for (int mi = 0; mi < 2; mi++)
            #pragma unroll
            for (int ni = 0; ni < 8; ni++) {
                mma16816(c[mi][ni], ah[mi][0], ah[mi][1], ah[mi][2], ah[mi][3], bh[ni][0], bh[ni][1]);
                mma16816(c[mi][ni], ah[mi][0], ah[mi][1], ah[mi][2], ah[mi][3], bl[ni][0], bl[ni][1]);
                mma16816(c[mi][ni], al[mi][0], al[mi][1], al[mi][2], al[mi][3], bh[ni][0], bh[ni][1]);
            }
    }
    #pragma unroll
    for (int mi = 0; mi < 2; mi++) {
        #pragma unroll
        for (int ni = 0; ni < 8; ni++) {
            int col = wn * 64 + ni * 8 + c_col2;
            int row = wm * 32 + mi * 16 + c_row;
            float bb0 = __ldg(&b_in[col]), bb1 = __ldg(&b_in[col + 1]);
            #pragma unroll
            for (int half = 0; half < 2; half++) {
                int r = row + half * 8;
                float x0 = c[mi][ni][half * 2]     + bb0;
                float x1 = c[mi][ni][half * 2 + 1] + bb1;
                __nv_bfloat16 h0, l0, h1, l1;
                split_bf16(x0, h0, l0); split_bf16(x1, h1, l1);
                __nv_bfloat162 ph; ph.x = h0; ph.y = h1;
                __nv_bfloat162 pl; pl.x = l0; pl.y = l1;
                *reinterpret_cast<__nv_bfloat162*>(&sXh[r * XSTR + col]) = ph;
                *reinterpret_cast<__nv_bfloat162*>(&sXl[r * XSTR + col]) = pl;
            }
        }
    }

    float c3[2][8][4];
    #pragma unroll
    for (int i = 0; i < 2; i++)
        #pragma unroll
        for (int j = 0; j < 8; j++)
            #pragma unroll
            for (int q = 0; q < 4; q++) c3[i][j][q] = 0.f;

    #pragma unroll 1
    for (int hc = 0; hc < 4; hc++) {
        __syncthreads();
        #pragma unroll
        for (int t = 0; t < 4; t++) {
            int idx = t * 256 + tid;
            int row = idx >> 4, c8 = (idx & 15) * 8;
            *reinterpret_cast<float4*>(&sBh[row * XSTR + c8]) =
                *reinterpret_cast<const float4*>(&g_w1_hi[(hc * 64 + row) * DM + c8]);
            *reinterpret_cast<float4*>(&sBl[row * XSTR + c8]) =
                *reinterpret_cast<const float4*>(&g_w1_lo[(hc * 64 + row) * DM + c8]);
        }
        __syncthreads();
        float c2[2][4][4];
        #pragma unroll
        for (int i = 0; i < 2; i++)
            #pragma unroll
            for (int j = 0; j < 4; j++)
                #pragma unroll
                for (int q = 0; q < 4; q++) c2[i][j][q] = 0.f;
        #pragma unroll
        for (int ks = 0; ks < 8; ks++) {
            const int kb = ks * 16;
            uint32_t ah[2][4], al[2][4];
            #pragma unroll
            for (int mi = 0; mi < 2; mi++) {
                uint32_t off = (uint32_t)((wm * 32 + mi * 16 + a_row) * XSTR + kb + a_half * 8) * 2;
                ldsm4(ah[mi][0], ah[mi][1], ah[mi][2], ah[mi][3], uXh + off);
                ldsm4(al[mi][0], al[mi][1], al[mi][2], al[mi][3], uXl + off);
            }
            uint32_t bh[4][2], bl[4][2];
            #pragma unroll
            for (int nq = 0; nq < 2; nq++) {
                uint32_t off = (uint32_t)((wn * 32 + nq * 16 + b_nt * 8 + b_row) * XSTR + kb + b_kh * 8) * 2;
                uint32_t r0, r1, r2, r3;
                ldsm4(r0, r1, r2, r3, uBh + off);
                bh[nq * 2][0] = r0; bh[nq * 2][1] = r1;
                bh[nq * 2 + 1][0] = r2; bh[nq * 2 + 1][1] = r3;
                ldsm4(r0, r1, r2, r3, uBl + off);
                bl[nq * 2][0] = r0; bl[nq * 2][1] = r1;
                bl[nq * 2 + 1][0] = r2; bl[nq * 2 + 1][1] = r3;
            }
            #pragma unroll
            for (int mi = 0; mi < 2; mi++)
                #pragma unroll
                for (int ni = 0; ni < 4; ni++) {
                    mma16816(c2[mi][ni], ah[mi][0], ah[mi][1], ah[mi][2], ah[mi][3], bh[ni][0], bh[ni][1]);
                    mma16816(c2[mi][ni], ah[mi][0], ah[mi][1], ah[mi][2], ah[mi][3], bl[ni][0], bl[ni][1]);
                    mma16816(c2[mi][ni], al[mi][0], al[mi][1], al[mi][2], al[mi][3], bh[ni][0], bh[ni][1]);
                }
        }
        #pragma unroll
        for (int mi = 0; mi < 2; mi++) {
            #pragma unroll
            for (int ni = 0; ni < 4; ni++) {
                int col = wn * 32 + ni * 8 + c_col2;
                int row = wm * 32 + mi * 16 + c_row;
                float bb0 = __ldg(&b1[hc * 64 + col]), bb1 = __ldg(&b1[hc * 64 + col + 1]);
                #pragma unroll
                for (int half = 0; half < 2; half++) {
                    int r = row + half * 8;
                    float h0 = fmaxf(c2[mi][ni][half * 2]     + bb0, 0.f);
                    float h1 = fmaxf(c2[mi][ni][half * 2 + 1] + bb1, 0.f);
                    __nv_bfloat16 hh0, ll0, hh1, ll1;
                    split_bf16(h0, hh0, ll0); split_bf16(h1, hh1, ll1);
                    __nv_bfloat162 ph; ph.x = hh0; ph.y = hh1;
                    __nv_bfloat162 pl; pl.x = ll0; pl.y = ll1;
                    *reinterpret_cast<__nv_bfloat162*>(&sAh[r * ASTR + col]) = ph;
                    *reinterpret_cast<__nv_bfloat162*>(&sAl[r * ASTR + col]) = pl;
                }
            }
        }
        __syncthreads();
        #pragma unroll
        for (int t = 0; t < 4; t++) {
            int idx = t * 256 + tid;
            int row = idx >> 3, c8 = (idx & 7) * 8;
            *reinterpret_cast<float4*>(&sBh[row * ASTR + c8]) =
                *reinterpret_cast<const float4*>(&g_w2_hi[row * DB + hc * 64 + c8]);
            *reinterpret_cast<float4*>(&sBl[row * ASTR + c8]) =
                *reinterpret_cast<const float4*>(&g_w2_lo[row * DB + hc * 64 + c8]);
        }
        __syncthreads();
        #pragma unroll
        for (int ks = 0; ks < 4; ks++) {
            const int kb = ks * 16;
            uint32_t ah[2][4], al[2][4];
            #pragma unroll
            for (int mi = 0; mi < 2; mi++) {
                uint32_t off = (uint32_t)((wm * 32 + mi * 16 + a_row) * ASTR + kb + a_half * 8) * 2;
                ldsm4(ah[mi][0], ah[mi][1], ah[mi][2], ah[mi][3], uAh + off);
                ldsm4(al[mi][0], al[mi][1], al[mi][2], al[mi][3], uAl + off);
            }
            uint32_t bh[8][2], bl[8][2];
            #pragma unroll
            for (int nq = 0; nq < 4; nq++) {
                uint32_t off = (uint32_t)((wn * 64 + nq * 16 + b_nt * 8 + b_row) * ASTR + kb + b_kh * 8) * 2;
                uint32_t r0, r1, r2, r3;
                ldsm4(r0, r1, r2, r3, uBh + off);
                bh[nq * 2][0] = r0; bh[nq * 2][1] = r1;
                bh[nq * 2 + 1][0] = r2; bh[nq * 2 + 1][1] = r3;
                ldsm4(r0, r1, r2, r3, uBl + off);
                bl[nq * 2][0] = r0; bl[nq * 2][1] = r1;
                bl[nq * 2 + 1][0] = r2; bl[nq * 2 + 1][1] = r3;
            }
            #pragma unroll
            for (int mi = 0; mi < 2; mi++)
                #pragma unroll
                for (int ni = 0; ni < 8; ni++) {
                    mma16816(c3[mi][ni], ah[mi][0], ah[mi][1], ah[mi][2], ah[mi][3], bh[ni][0], bh[ni][1]);
                    mma16816(c3[mi][ni], ah[mi][0], ah[mi][1], ah[mi][2], ah[mi][3], bl[ni][0], bl[ni][1]);
                    mma16816(c3[mi][ni], al[mi][0], al[mi][1], al[mi][2], al[mi][3], bh[ni][0], bh[ni][1]);
                }
        }
    }

    #pragma unroll
    for (int mi = 0; mi < 2; mi++) {
        #pragma unroll
        for (int ni = 0; ni < 8; ni++) {
            int col = wn * 64 + ni * 8 + c_col2;
            int row = wm * 32 + mi * 16 + c_row;
            float bb0 = __ldg(&b2[col]), bb1 = __ldg(&b2[col + 1]);
            #pragma unroll
            for (int half = 0; half < 2; half++) {
                int r = row + half * 8;
                __nv_bfloat162 ph = *reinterpret_cast<__nv_bfloat162*>(&sXh[r * XSTR + col]);
                __nv_bfloat162 pl = *reinterpret_cast<__nv_bfloat162*>(&sXl[r * XSTR + col]);
                float x0 = bf2f(ph.x) + bf2f(pl.x) + c3[mi][ni][half * 2]     + bb0;
                float x1 = bf2f(ph.y) + bf2f(pl.y) + c3[mi][ni][half * 2 + 1] + bb1;
                if (!cand)
                    *reinterpret_cast<float2*>(&g_xb[(size_t)(row0 + r) * DM + col]) =
                        make_float2(x0, x1);
                __nv_bfloat16 h0, l0, h1, l1;
                split_bf16(x0, h0, l0); split_bf16(x1, h1, l1);
                ph.x = h0; ph.y = h1; pl.x = l0; pl.y = l1;
                *reinterpret_cast<__nv_bfloat162*>(&sXh[r * XSTR + col]) = ph;
                *reinterpret_cast<__nv_bfloat162*>(&sXl[r * XSTR + col]) = pl;
            }
        }
    }
    __syncthreads();

    for (int r = w; r < 128; r += 8) {
        float v[4];
        #pragma unroll
        for (int i = 0; i < 4; i++) {
            int cc = lane + 32 * i;
            v[i] = bf2f(sXh[r * XSTR + cc]) + bf2f(sXl[r * XSTR + cc]);
        }
        float s = v[0] + v[1] + v[2] + v[3];
        #pragma unroll
        for (int o = 16; o; o >>= 1) s += __shfl_xor_sync(0xffffffffu, s, o);
        float mu = s * (1.f / 128.f);
        float d[4] = {v[0] - mu, v[1] - mu, v[2] - mu, v[3] - mu};
        float q = d[0] * d[0] + d[1] * d[1] + d[2] * d[2] + d[3] * d[3];
        #pragma unroll
        for (int o = 16; o; o >>= 1) q += __shfl_xor_sync(0xffffffffu, q, o);
        float rstd = rsqrtf(q * (1.f / 128.f) + 1e-5f);
        #pragma unroll
        for (int i = 0; i < 4; i++) {
            int cc = lane + 32 * i;
            float ln = d[i] * rstd * __ldg(&mg[cc]) + __ldg(&mb[cc]);
            __nv_bfloat16 h, l; split_bf16(ln, h, l);
            sXh[r * XSTR + cc] = h;
            sXl[r * XSTR + cc] = l;
        }
    }

    #pragma unroll
    for (int i = 0; i < 2; i++)
        #pragma unroll
        for (int j = 0; j < 8; j++)
            #pragma unroll
            for (int q = 0; q < 4; q++) c[i][j][q] = 0.f;
    #pragma unroll 1
    for (int kc2 = 0; kc2 < 2; kc2++) {
        __syncthreads();
        #pragma unroll
        for (int t = 0; t < 4; t++) {
            int idx = t * 256 + tid;
            int row = idx >> 3, c8 = (idx & 7) * 8;
            *reinterpret_cast<float4*>(&sBh[row * ASTR + c8]) =
                *reinterpret_cast<const float4*>(&g_wk_hi[row * DM + kc2 * 64 + c8]);
            *reinterpret_cast<float4*>(&sBl[row * ASTR + c8]) =
                *reinterpret_cast<const float4*>(&g_wk_lo[row * DM + kc2 * 64 + c8]);
        }
        __syncthreads();
        #pragma unroll
        for (int ks = 0; ks < 4; ks++) {
            const int kb = ks * 16;
            uint32_t ah[2][4], al[2][4];
            #pragma unroll
            for (int mi = 0; mi < 2; mi++) {
                uint32_t off = (uint32_t)((wm * 32 + mi * 16 + a_row) * XSTR + kc2 * 64 + kb + a_half * 8) * 2;
                ldsm4(ah[mi][0], ah[mi][1], ah[mi][2], ah[mi][3], uXh + off);
                ldsm4(al[mi][0], al[mi][1], al[mi][2], al[mi][3], uXl + off);
            }
            uint32_t bh[8][2], bl[8][2];
            #pragma unroll
            for (int nq = 0; nq < 4; nq++) {
                uint32_t off = (uint32_t)((wn * 64 + nq * 16 + b_nt * 8 + b_row) * ASTR + kb + b_kh * 8) * 2;
                uint32_t r0, r1, r2, r3;
                ldsm4(r0, r1, r2, r3, uBh + off);
                bh[nq * 2][0] = r0; bh[nq * 2][1] = r1;
                bh[nq * 2 + 1][0] = r2; bh[nq * 2 + 1][1] = r3;
                ldsm4(r0, r1, r2, r3, uBl + off);
                bl[nq * 2][0] = r0; bl[nq * 2][1] = r1;
                bl[nq * 2 + 1][0] = r2; bl[nq * 2 + 1][1] = r3;
            }
            #pragma unroll
            for (int mi = 0; mi < 2; mi++)
                #pragma unroll
                for (int ni = 0; ni < 8; ni++) {
                    mma16816(c[mi][ni], ah[mi][0], ah[mi][1], ah[mi][2], ah[mi][3], bh[ni][0], bh[ni][1]);
                    mma16816(c[mi][ni], ah[mi][0], ah[mi][1], ah[mi][2], ah[mi][3], bl[ni][0], bl[ni][1]);
                    mma16816(c[mi][ni], al[mi][0], al[mi][1], al[mi][2], al[mi][3], bh[ni][0], bh[ni][1]);
                }
        }
    }
    __syncthreads();
    #pragma unroll
    for (int mi = 0; mi < 2; mi++) {
        #pragma unroll
        for (int ni = 0; ni < 8; ni++) {
            int col = wn * 64 + ni * 8 + c_col2;
            int row = wm * 32 + mi * 16 + c_row;
            float bb0 = __ldg(&bk[col]), bb1 = __ldg(&bk[col + 1]);
            #pragma unroll
            for (int half = 0; half < 2; half++) {
                int r = row + half * 8;
                float k0 = c[mi][ni][half * 2]     + bb0;
                float k1 = c[mi][ni][half * 2 + 1] + bb1;
                __nv_bfloat16 h0, l0, h1, l1;
                split_bf16(k0, h0, l0); split_bf16(k1, h1, l1);
                __nv_bfloat162 ph; ph.x = h0; ph.y = h1;
                __nv_bfloat162 pl; pl.x = l0; pl.y = l1;
                *reinterpret_cast<__nv_bfloat162*>(&sXh[r * XSTR + col]) = ph;
                *reinterpret_cast<__nv_bfloat162*>(&sXl[r * XSTR + col]) = pl;
            }
        }
    }
    __syncthreads();

    {
        const float scale = cand ? 1.f : 2.f;
        float* out_k = cand ? g_cand_k : g_kb;
        __nv_bfloat16* out_hi = cand ? g_ck_hi : g_kb_hi;
        __nv_bfloat16* out_lo = cand ? g_ck_lo : g_kb_lo;
        #pragma unroll
        for (int t = 0; t < 16; t++) {
            int idx = t * 256 + tid;
            int row = idx >> 5, q4 = (idx & 31) * 4;
            if (row < nrows) {
                ull uh = *reinterpret_cast<ull*>(&sXh[row * XSTR + q4]);
                ull ul = *reinterpret_cast<ull*>(&sXl[row * XSTR + q4]);
                __nv_bfloat16* hp = reinterpret_cast<__nv_bfloat16*>(&uh);
                __nv_bfloat16* lp = reinterpret_cast<__nv_bfloat16*>(&ul);
                float kv[4];
                __nv_bfloat16 oh[4], ol[4];
                #pragma unroll
                for (int e = 0; e < 4; e++) {
                    kv[e] = bf2f(hp[e]) + bf2f(lp[e]);
                    split_bf16(scale * kv[e], oh[e], ol[e]);
                }
                size_t base = (size_t)(row0 + row) * DM + q4;
                *reinterpret_cast<float4*>(&out_k[base]) =
                    make_float4(kv[0], kv[1], kv[2], kv[3]);
                *reinterpret_cast<ull*>(&out_hi[base]) = *reinterpret_cast<ull*>(oh);
                *reinterpret_cast<ull*>(&out_lo[base]) = *reinterpret_cast<ull*>(ol);
            }
        }
    }
    if (cand) {
        for (int r = w; r < 128; r += 8) {
            float q = 0.f;
            #pragma unroll
            for (int i = 0; i < 4; i++) {
                int cc = lane + 32 * i;
                float v = bf2f(sXh[r * XSTR + cc]) + bf2f(sXl[r * XSTR + cc]);
                q += v * v;
            }
            #pragma unroll
            for (int o = 16; o; o >>= 1) q += __shfl_xor_sync(0xffffffffu, q, o);
            if (lane == 0 && r < nrows) g_cand_cn[row0 + r] = q;
        }
    }
}

// ============================================================
// sims via mma.sync bf16 split GEMM; epilogue also emits
// per-(row, 32-col-block) maxima into g_bmax.
// ============================================================
__global__ void __launch_bounds__(256) sims_mma_kernel()
{
    extern __shared__ __nv_bfloat16 sm[];
    __nv_bfloat16* sAh = sm;
    __nv_bfloat16* sAl = sAh + BM * ASTR;
    __nv_bfloat16* sBh = sAl + BM * ASTR;
    __nv_bfloat16* sBl = sBh + BM * ASTR;

    const int tid  = threadIdx.x;
    const int lane = tid & 31;
    const int w    = tid >> 5;
    const int wm   = w & 3;
    const int wn   = w >> 2;
    const int m0 = blockIdx.y * BM;
    const int n0 = blockIdx.x * BN;

    const uint32_t uAh = smem_u32(sAh), uAl = smem_u32(sAl);
    const uint32_t uBh = smem_u32(sBh), uBl = smem_u32(sBl);

    float c[2][8][4];
    #pragma unroll
    for (int i = 0; i < 2; i++)
        #pragma unroll
        for (int j = 0; j < 8; j++)
            #pragma unroll
            for (int q = 0; q < 4; q++) c[i][j][q] = 0.f;

    const int a_row = lane & 15, a_half = lane >> 4;
    const int b_grp = lane >> 3, b_row = lane & 7;
    const int b_nt = b_grp >> 1, b_kh = b_grp & 1;

    #pragma unroll 1
    for (int ch = 0; ch < 2; ch++) {
        const int kc = ch * BK;
        #pragma unroll
        for (int t = 0; t < 4; t++) {
            int idx = t * 256 + tid;
            int row = idx >> 3, c8 = (idx & 7) * 8;
            *reinterpret_cast<float4*>(&sAh[row * ASTR + c8]) =
                *reinterpret_cast<const float4*>(&g_kb_hi[(m0 + row) * DM + kc + c8]);
            *reinterpret_cast<float4*>(&sAl[row * ASTR + c8]) =
                *reinterpret_cast<const float4*>(&g_kb_lo[(m0 + row) * DM + kc + c8]);
        }
        #pragma unroll
        for (int t = 0; t < 4; t++) {
            int idx = t * 256 + tid;
            int row = idx >> 3, c8 = (idx & 7) * 8;
            int col = n0 + row;
            float4 vh = make_float4(0.f, 0.f, 0.f, 0.f), vl = vh;
            if (col < NC) {
                vh = *reinterpret_cast<const float4*>(&g_ck_hi[(size_t)col * DM + kc + c8]);
                vl = *reinterpret_cast<const float4*>(&g_ck_lo[(size_t)col * DM + kc + c8]);
            }
            *reinterpret_cast<float4*>(&sBh[row * ASTR + c8]) = vh;
            *reinterpret_cast<float4*>(&sBl[row * ASTR + c8]) = vl;
        }
        __syncthreads();

        #pragma unroll
        for (int ks = 0; ks < BK / 16; ks++) {
            const int kb = ks * 16;
            uint32_t ah[2][4], al[2][4];
            #pragma unroll
            for (int mi = 0; mi < 2; mi++) {
                uint32_t off = (uint32_t)((wm * 32 + mi * 16 + a_row) * ASTR + kb + a_half * 8) * 2;
                ldsm4(ah[mi][0], ah[mi][1], ah[mi][2], ah[mi][3], uAh + off);
                ldsm4(al[mi][0], al[mi][1], al[mi][2], al[mi][3], uAl + off);
            }
            uint32_t bh[8][2], bl[8][2];
            #pragma unroll
            for (int nq = 0; nq < 4; nq++) {
                uint32_t off = (uint32_t)((wn * 64 + nq * 16 + b_nt * 8 + b_row) * ASTR + kb + b_kh * 8) * 2;
                uint32_t r0, r1, r2, r3;
                ldsm4(r0, r1, r2, r3, uBh + off);
                bh[nq * 2][0] = r0; bh[nq * 2][1] = r1;
                bh[nq * 2 + 1][0] = r2; bh[nq * 2 + 1][1] = r3;
                ldsm4(r0, r1, r2, r3, uBl + off);
                bl[nq * 2][0] = r0; bl[nq * 2][1] = r1;
                bl[nq * 2 + 1][0] = r2; bl[nq * 2 + 1][1] = r3;
            }
            #pragma unroll
            for (int mi = 0; mi < 2; mi++)
                #pragma unroll
                for (int ni = 0; ni < 8; ni++) {
                    mma16816(c[mi][ni], ah[mi][0], ah[mi][1], ah[mi][2], ah[mi][3], bh[ni][0], bh[ni][1]);
                    mma16816(c[mi][ni], ah[mi][0], ah[mi][1], ah[mi][2], ah[mi][3], bl[ni][0], bl[ni][1]);
                    mma16816(c[mi][ni], al[mi][0], al[mi][1], al[mi][2], al[mi][3], bh[ni][0], bh[ni][1]);
                }
        }
        __syncthreads();
    }

    const int col_base = n0 + wn * 64 + (lane & 3) * 2;
    float2 cn[8];
    #pragma unroll
    for (int ni = 0; ni < 8; ni++) {
        int col = col_base + ni * 8;
        cn[ni].x = (col < NC) ? __ldg(&g_cand_cn[col]) : 0.f;
        cn[ni].y = (col < NC) ? __ldg(&g_cand_cn[col + 1]) : 0.f;
    }
    #pragma unroll
    for (int mi = 0; mi < 2; mi++) {
        int row = m0 + wm * 32 + mi * 16 + (lane >> 2);
        float* d0 = &g_sims[(size_t)row * NC];
        float* d1 = &g_sims[(size_t)(row + 8) * NC];
        float bmA[2] = {-3.4e38f, -3.4e38f};
        float bmB[2] = {-3.4e38f, -3.4e38f};
        #pragma unroll
        for (int ni = 0; ni < 8; ni++) {
            int col = col_base + ni * 8;
            if (col < NC) {
                float v00 = c[mi][ni][0] - cn[ni].x, v01 = c[mi][ni][1] - cn[ni].y;
                float v10 = c[mi][ni][2] - cn[ni].x, v11 = c[mi][ni][3] - cn[ni].y;
                *reinterpret_cast<float2*>(d0 + col) = make_float2(v00, v01);
                *reinterpret_cast<float2*>(d1 + col) = make_float2(v10, v11);
                int b = ni >> 2;
                bmA[b] = fmaxf(bmA[b], fmaxf(v00, v01));
                bmB[b] = fmaxf(bmB[b], fmaxf(v10, v11));
            }
        }
        #pragma unroll
        for (int b = 0; b < 2; b++) {
            float ma = bmA[b], mb2 = bmB[b];
            ma  = fmaxf(ma,  __shfl_xor_sync(0xffffffffu, ma, 1));
            ma  = fmaxf(ma,  __shfl_xor_sync(0xffffffffu, ma, 2));
            mb2 = fmaxf(mb2, __shfl_xor_sync(0xffffffffu, mb2, 1));
            mb2 = fmaxf(mb2, __shfl_xor_sync(0xffffffffu, mb2, 2));
            int cb = n0 + wn * 64 + b * 32;
            if ((lane & 3) == 0 && cb < NC) {
                int blk = cb >> 5;
                g_bmax[(size_t)row * BSTR + blk] = ma;
                g_bmax[(size_t)(row + 8) * BSTR + blk] = mb2;
            }
        }
    }
}

// ============================================================
// Block-max assisted exact top-96.
// ============================================================
__device__ __forceinline__ unsigned f2k(float f) {
    unsigned u = __float_as_uint(f);
    return (u & 0x80000000u) ? ~u : (u | 0x80000000u);
}

// exact 32-bit radix select over smem-resident keys (3 levels: 12/12/8).
// returns key T s.t. count(>T) < need <= count(>=T); *need_eq = need - count(>T)
__device__ unsigned radix_select(const unsigned* __restrict__ keys, int n, int need,
                                 unsigned* hist, unsigned* psum,
                                 int* s_bin, int* s_need, int tid, int* need_eq)
{
    // level 1: bits [31:20]
    for (int i = tid; i < 4096; i += 256) hist[i] = 0;
    __syncthreads();
    for (int i = tid; i < n; i += 256) atomicAdd(&hist[keys[i] >> 20], 1u);
    __syncthreads();
    if (tid < 128) {
        unsigned s = 0;
        for (int j = 0; j < 32; j++) s += hist[tid * 32 + j];
        psum[tid] = s;
    }
    __syncthreads();
    if (tid == 0) {
        int nd = need; unsigned cum = 0; int g = 127;
        for (; g >= 0; g--) { if (cum + psum[g] >= (unsigned)nd) break; cum += psum[g]; }
        for (int j = 31; j >= 0; j--) {
            unsigned c = hist[g * 32 + j];
            if (cum + c >= (unsigned)nd) { *s_bin = g * 32 + j; *s_need = nd - (int)cum; break; }
            cum += c;
        }
    }
    __syncthreads();
    const unsigned b1 = (unsigned)*s_bin;
    const int need1 = *s_need;
    __syncthreads();
    // level 2: bits [19:8]
    for (int i = tid; i < 4096; i += 256) hist[i] = 0;
    __syncthreads();
    for (int i = tid; i < n; i += 256) {
        unsigned k = keys[i];
        if ((k >> 20) == b1) atomicAdd(&hist[(k >> 8) & 0xFFFu], 1u);
    }
    __syncthreads();
    if (tid < 128) {
        unsigned s = 0;
        for (int j = 0; j < 32; j++) s += hist[tid * 32 + j];
        psum[tid] = s;
    }
    __syncthreads();
    if (tid == 0) {
        int nd = need1; unsigned cum = 0; int g = 127;
        for (; g >= 0; g--) { if (cum + psum[g] >= (unsigned)nd) break; cum += psum[g]; }
        for (int j = 31; j >= 0; j--) {
            unsigned c = hist[g * 32 + j];
            if (cum + c >= (unsigned)nd) { *s_bin = g * 32 + j; *s_need = nd - (int)cum; break; }
            cum += c;
        }
    }
    __syncthreads();
    const unsigned b2 = (unsigned)*s_bin;
    const int need2 = *s_need;
    const unsigned p2 = (b1 << 12) | b2;
    __syncthreads();
    // level 3: bits [7:0]
    for (int i = tid; i < 256; i += 256) hist[i] = 0;
    __syncthreads();
    for (int i = tid; i < n; i += 256) {
        unsigned k = keys[i];
        if ((k >> 8) == p2) atomicAdd(&hist[k & 0xFFu], 1u);
    }
    __syncthreads();
    if (tid == 0) {
        int nd = need2; unsigned cum = 0;
        for (int j = 255; j >= 0; j--) {
            unsigned c = hist[j];
            if (cum + c >= (unsigned)nd) { *s_bin = j; *s_need = nd - (int)cum; break; }
            cum += c;
        }
    }
    __syncthreads();
    unsigned T = (p2 << 8) | (unsigned)*s_bin;
    *need_eq = *s_need;
    __syncthreads();
    return T;
}

__global__ void __launch_bounds__(256) topk_kernel()
{
    const int row = blockIdx.x;
    const int tid = threadIdx.x;
    extern __shared__ unsigned tsm[];
    unsigned* s_keys = tsm;                      // 3136
    unsigned* hist   = s_keys + 3136;            // 4096
    float*    s_cv   = (float*)(hist + 4096);    // 4096
    int*      s_ci   = (int*)(s_cv + 4096);      // 4096
    unsigned* s_ck   = (unsigned*)(s_ci + 4096); // 4096
    int*      s_blk  = (int*)(s_ck + 4096);      // BCAP
    __shared__ unsigned psum[128];
    __shared__ int s_bin, s_need, s_nblk, s_cnt, s_eqc;
    __shared__ float s_vals[CTXN];
    __shared__ int s_ids[CTXN];
    __shared__ float s_red;

    // ---- load block-max keys
    const float* bmax = g_bmax + (size_t)row * BSTR;
    for (int i = tid; i < NBLKS; i += 256) s_keys[i] = f2k(bmax[i]);
    if (tid == 0) s_nblk = 0;
    __syncthreads();

    // ---- exact 96th-largest block max
    int dmy;
    unsigned Tb = radix_select(s_keys, NBLKS, CTXN, hist, psum, &s_bin, &s_need, tid, &dmy);

    // ---- gather candidate block ids (>= Tb). #blocks == 96 barring exact
    // fp32 blockmax ties (measure-zero for continuous data); cap at BCAP.
    for (int i = tid; i < NBLKS; i += 256) {
        if (s_keys[i] >= Tb) {
            int p = atomicAdd(&s_nblk, 1);
            if (p < BCAP) s_blk[p] = i;
        }
    }
    __syncthreads();
    const int nblk = min(s_nblk, BCAP);
    const int ncand = nblk * 32;

    // ---- gather candidate elements (coalesced 128B per block)
    const float* sims = g_sims + (size_t)row * NC;
    for (int j = tid; j < ncand; j += 256) {
        int blk = s_blk[j >> 5];
        int idx = blk * 32 + (j & 31);
        float v = sims[idx];
        s_cv[j] = v;
        s_ci[j] = idx;
        s_ck[j] = f2k(v);
    }
    if (tid == 0) { s_cnt = 0; s_eqc = 0; }
    __syncthreads();

    // ---- exact top-96 among candidates
    int need_eq;
    unsigned T = radix_select(s_ck, ncand, CTXN, hist, psum, &s_bin, &s_need, tid, &need_eq);

    for (int j = tid; j < ncand; j += 256) {
        unsigned k = s_ck[j];
        if (k > T) {
            int p = atomicAdd(&s_cnt, 1);
            s_vals[p] = s_cv[j]; s_ids[p] = s_ci[j];
        } else if (k == T) {
            int q = atomicAdd(&s_eqc, 1);
            if (q < need_eq) {
                int p = atomicAdd(&s_cnt, 1);
                s_vals[p] = s_cv[j]; s_ids[p] = s_ci[j];
            }
        }
    }
    __syncthreads();

    // ---- softmax over 96
    if (tid == 0) {
        float m = -3.4e38f;
        for (int i = 0; i < CTXN; i++) m = fmaxf(m, s_vals[i]);
        s_red = m;
    }
    __syncthreads();
    float m = s_red;
    if (tid < CTXN) s_vals[tid] = expf(s_vals[tid] - m);
    __syncthreads();
    if (tid == 0) {
        float s = 0.f;
        for (int i = 0; i < CTXN; i++) s += s_vals[i];
        s_red = 1.f / s;
    }
    __syncthreads();
    if (tid < CTXN) {
        g_probs[row * CTXN + tid] = s_vals[tid] * s_red;
        g_tidx [row * CTXN + tid] = s_ids[tid];
    }
}

// ============================================================
// ctx GEMM1 (unchanged)
// ============================================================
__global__ void __launch_bounds__(256) ctx_mma1_kernel(
    const float* __restrict__ bt1)
{
    extern __shared__ __nv_bfloat16 sm[];
    __nv_bfloat16* sAh = sm;
    __nv_bfloat16* sAl = sAh + BM * ASTR;
    __nv_bfloat16* sBh = sAl + BM * ASTR;
    __nv_bfloat16* sBl = sBh + BM * ASTR;

    const int tid  = threadIdx.x;
    const int lane = tid & 31;
    const int w    = tid >> 5;
    const int wm   = w & 3;
    const int wn   = w >> 2;
    const int m0 = blockIdx.y * BM;
    const int n0 = blockIdx.x * BN;

    const uint32_t uAh = smem_u32(sAh), uAl = smem_u32(sAl);
    const uint32_t uBh = smem_u32(sBh), uBl = smem_u32(sBl);

    float c[2][8][4];
    #pragma unroll
    for (int i = 0; i < 2; i++)
        #pragma unroll
        for (int j = 0; j < 8; j++)
            #pragma unroll
            for (int q = 0; q < 4; q++) c[i][j][q] = 0.f;

    const int a_row = lane & 15, a_half = lane >> 4;
    const int b_grp = lane >> 3, b_row = lane & 7;
    const int b_nt = b_grp >> 1, b_kh = b_grp & 1;

    #pragma unroll 1
    for (int ch = 0; ch < 2; ch++) {
        const int kc = ch * BK;
        #pragma unroll
        for (int t = 0; t < 8; t++) {
            int idx = t * 256 + tid;
            int row = idx >> 4, q4 = (idx & 15) * 4;
            int p = m0 + row;
            int b = p / CTXN;
            int ci = g_tidx[p];
            float4 kv = *reinterpret_cast<const float4*>(&g_kb[(size_t)b * DM + kc + q4]);
            float4 cv = *reinterpret_cast<const float4*>(&g_cand_k[(size_t)ci * DM + kc + q4]);
            float d[4] = {kv.x - cv.x, kv.y - cv.y, kv.z - cv.z, kv.w - cv.w};
            __nv_bfloat16 hh[4], ll[4];
            #pragma unroll
            for (int e = 0; e < 4; e++) split_bf16(d[e], hh[e], ll[e]);
            *reinterpret_cast<ull*>(&sAh[row * ASTR + q4]) = *reinterpret_cast<ull*>(hh);
            *reinterpret_cast<ull*>(&sAl[row * ASTR + q4]) = *reinterpret_cast<ull*>(ll);
        }
        #pragma unroll
        for (int t = 0; t < 4; t++) {
            int idx = t * 256 + tid;
            int row = idx >> 3, c8 = (idx & 7) * 8;
            *reinterpret_cast<float4*>(&sBh[row * ASTR + c8]) =
                *reinterpret_cast<const float4*>(&g_wt1_hi[(n0 + row) * DM + kc + c8]);
            *reinterpret_cast<float4*>(&sBl[row * ASTR + c8]) =
                *reinterpret_cast<const float4*>(&g_wt1_lo[(n0 + row) * DM + kc + c8]);
        }
        __syncthreads();

        #pragma unroll
        for (int ks = 0; ks < BK / 16; ks++) {
            const int kb = ks * 16;
            uint32_t ah[2][4], al[2][4];
            #pragma unroll
            for (int mi = 0; mi < 2; mi++) {
                uint32_t off = (uint32_t)((wm * 32 + mi * 16 + a_row) * ASTR + kb + a_half * 8) * 2;
                ldsm4(ah[mi][0], ah[mi][1], ah[mi][2], ah[mi][3], uAh + off);
                ldsm4(al[mi][0], al[mi][1], al[mi][2], al[mi][3], uAl + off);
            }
            uint32_t bh[8][2], bl[8][2];
            #pragma unroll
            for (int nq = 0; nq < 4; nq++) {
                uint32_t off = (uint32_t)((wn * 64 + nq * 16 + b_nt * 8 + b_row) * ASTR + kb + b_kh * 8) * 2;
                uint32_t r0, r1, r2, r3;
                ldsm4(r0, r1, r2, r3, uBh + off);
                bh[nq * 2][0] = r0; bh[nq * 2][1] = r1;
                bh[nq * 2 + 1][0] = r2; bh[nq * 2 + 1][1] = r3;
                ldsm4(r0, r1, r2, r3, uBl + off);
                bl[nq * 2][0] = r0; bl[nq * 2][1] = r1;
                bl[nq * 2 + 1][0] = r2; bl[nq * 2 + 1][1] = r3;
            }
            #pragma unroll
            for (int mi = 0; mi < 2; mi++)
                #pragma unroll
                for (int ni = 0; ni < 8; ni++) {
                    mma16816(c[mi][ni], ah[mi][0], ah[mi][1], ah[mi][2], ah[mi][3], bh[ni][0], bh[ni][1]);
                    mma16816(c[mi][ni], ah[mi][0], ah[mi][1], ah[mi][2], ah[mi][3], bl[ni][0], bl[ni][1]);
                    mma16816(c[mi][ni], al[mi][0], al[mi][1], al[mi][2], al[mi][3], bh[ni][0], bh[ni][1]);
                }
        }
        __syncthreads();
    }

    const int col_base = n0 + wn * 64 + (lane & 3) * 2;
    #pragma unroll
    for (int mi = 0; mi < 2; mi++) {
        int row = m0 + wm * 32 + mi * 16 + (lane >> 2);
        #pragma unroll
        for (int ni = 0; ni < 8; ni++) {
            int col = col_base + ni * 8;
            float b0 = __ldg(&bt1[col]), b1v = __ldg(&bt1[col + 1]);
            float h00 = fmaxf(c[mi][ni][0] + b0, 0.f);
            float h01 = fmaxf(c[mi][ni][1] + b1v, 0.f);
            float h10 = fmaxf(c[mi][ni][2] + b0, 0.f);
            float h11 = fmaxf(c[mi][ni][3] + b1v, 0.f);
            __nv_bfloat16 h, l;
            __nv_bfloat162 ph, pl;
            split_bf16(h00, h, l); ph.x = h; pl.x = l;
            split_bf16(h01, h, l); ph.y = h; pl.y = l;
            *reinterpret_cast<__nv_bfloat162*>(&g_h_hi[(size_t)row * DB + col]) = ph;
            *reinterpret_cast<__nv_bfloat162*>(&g_h_lo[(size_t)row * DB + col]) = pl;
            split_bf16(h10, h, l); ph.x = h; pl.x = l;
            split_bf16(h11, h, l); ph.y = h; pl.y = l;
            *reinterpret_cast<__nv_bfloat162*>(&g_h_hi[(size_t)(row + 8) * DB + col]) = ph;
            *reinterpret_cast<__nv_bfloat162*>(&g_h_lo[(size_t)(row + 8) * DB + col]) = pl;
        }
    }
}

// ============================================================
// ctx GEMM2 (unchanged)
// ============================================================
__global__ void __launch_bounds__(256) ctx_mma2_kernel(
    const float* __restrict__ cand_y,
    const float* __restrict__ w_le, const float* __restrict__ b_le)
{
    extern __shared__ __nv_bfloat16 sm[];
    __nv_bfloat16* sAh = sm;
    __nv_bfloat16* sAl = sAh + BM * ASTR;
    __nv_bfloat16* sBh = sAl + BM * ASTR;
    __nv_bfloat16* sBl = sBh + BM * ASTR;

    const int tid  = threadIdx.x;
    const int lane = tid & 31;
    const int w    = tid >> 5;
    const int wm   = w & 3;
    const int wn   = w >> 2;
    const int m0 = blockIdx.y * BM;

    const uint32_t uAh = smem_u32(sAh), uAl = smem_u32(sAl);
    const uint32_t uBh = smem_u32(sBh), uBl = smem_u32(sBl);

    float c[2][8][4];
    #pragma unroll
    for (int i = 0; i < 2; i++)
        #pragma unroll
        for (int j = 0; j < 8; j++)
            #pragma unroll
            for (int q = 0; q < 4; q++) c[i][j][q] = 0.f;

    const int a_row = lane & 15, a_half = lane >> 4;
    const int b_grp = lane >> 3, b_row = lane & 7;
    const int b_nt = b_grp >> 1, b_kh = b_grp & 1;

    #pragma unroll 1
    for (int ch = 0; ch < 4; ch++) {
        const int kc = ch * BK;
        #pragma unroll
        for (int t = 0; t < 4; t++) {
            int idx = t * 256 + tid;
            int row = idx >> 3, c8 = (idx & 7) * 8;
            *reinterpret_cast<float4*>(&sAh[row * ASTR + c8]) =
                *reinterpret_cast<const float4*>(&g_h_hi[(size_t)(m0 + row) * DB + kc + c8]);
            *reinterpret_cast<float4*>(&sAl[row * ASTR + c8]) =
                *reinterpret_cast<const float4*>(&g_h_lo[(size_t)(m0 + row) * DB + kc + c8]);
        }
        #pragma unroll
        for (int t = 0; t < 4; t++) {
            int idx = t * 256 + tid;
            int row = idx >> 3, c8 = (idx & 7) * 8;
            *reinterpret_cast<float4*>(&sBh[row * ASTR + c8]) =
                *reinterpret_cast<const float4*>(&g_wt2_hi[row * DB + kc + c8]);
            *reinterpret_cast<float4*>(&sBl[row * ASTR + c8]) =
                *reinterpret_cast<const float4*>(&g_wt2_lo[row * DB + kc + c8]);
        }
        __syncthreads();

        #pragma unroll
        for (int ks = 0; ks < BK / 16; ks++) {
            const int kb = ks * 16;
            uint32_t ah[2][4], al[2][4];
            #pragma unroll
            for (int mi = 0; mi < 2; mi++) {
                uint32_t off = (uint32_t)((wm * 32 + mi * 16 + a_row) * ASTR + kb + a_half * 8) * 2;
                ldsm4(ah[mi][0], ah[mi][1], ah[mi][2], ah[mi][3], uAh + off);
                ldsm4(al[mi][0], al[mi][1], al[mi][2], al[mi][3], uAl + off);
            }
            uint32_t bh[8][2], bl[8][2];
            #pragma unroll
            for (int nq = 0; nq < 4; nq++) {
                uint32_t off = (uint32_t)((wn * 64 + nq * 16 + b_nt * 8 + b_row) * ASTR + kb + b_kh * 8) * 2;
                uint32_t r0, r1, r2, r3;
                ldsm4(r0, r1, r2, r3, uBh + off);
                bh[nq * 2][0] = r0; bh[nq * 2][1] = r1;
                bh[nq * 2 + 1][0] = r2; bh[nq * 2 + 1][1] = r3;
                ldsm4(r0, r1, r2, r3, uBl + off);
                bl[nq * 2][0] = r0; bl[nq * 2][1] = r1;
                bl[nq * 2 + 1][0] = r2; bl[nq * 2 + 1][1] = r3;
            }
            #pragma unroll
            for (int mi = 0; mi < 2; mi++)
                #pragma unroll
                for (int ni = 0; ni < 8; ni++) {
                    mma16816(c[mi][ni], ah[mi][0], ah[mi][1], ah[mi][2], ah[mi][3], bh[ni][0], bh[ni][1]);
                    mma16816(c[mi][ni], ah[mi][0], ah[mi][1], ah[mi][2], ah[mi][3], bl[ni][0], bl[ni][1]);
                    mma16816(c[mi][ni], al[mi][0], al[mi][1], al[mi][2], al[mi][3], bh[ni][0], bh[ni][1]);
                }
        }
        __syncthreads();
    }

    float* s_prob = reinterpret_cast<float*>(sm);
    float* s_y    = s_prob + BM;
    float* s_wle  = s_y + BM;
    float* s_ble  = s_wle + DM;
    if (tid < BM) {
        int p = m0 + tid;
        s_prob[tid] = g_probs[p];
        s_y[tid]    = __ldg(&cand_y[g_tidx[p]]);
    } else if (tid < BM + DM) {
        int j = tid - BM;
        s_wle[j] = __ldg(&w_le[j]);
        s_ble[j] = __ldg(&b_le[j]);
    }
    __syncthreads();

    const int col_base = wn * 64 + (lane & 3) * 2;
    #pragma unroll
    for (int mi = 0; mi < 2; mi++) {
        int r0 = wm * 32 + mi * 16 + (lane >> 2);
        int r1 = r0 + 8;
        float p0 = s_prob[r0], y0 = s_y[r0];
        float p1 = s_prob[r1], y1 = s_y[r1];
        #pragma unroll
        for (int ni = 0; ni < 8; ni++) {
            int col = col_base + ni * 8;
            float wl0 = s_wle[col], wl1 = s_wle[col + 1];
            float bl0 = s_ble[col], bl1 = s_ble[col + 1];
            *reinterpret_cast<float2*>(&g_vals[(size_t)(m0 + r0) * DM + col]) =
                make_float2(p0 * (y0 * wl0 + bl0 + c[mi][ni][0]),
                            p0 * (y0 * wl1 + bl1 + c[mi][ni][1]));
            *reinterpret_cast<float2*>(&g_vals[(size_t)(m0 + r1) * DM + col]) =
                make_float2(p1 * (y1 * wl0 + bl0 + c[mi][ni][2]),
                            p1 * (y1 * wl1 + bl1 + c[mi][ni][3]));
        }
    }
}

// Context reduce (unchanged)
__global__ void __launch_bounds__(128) ctx_reduce_kernel()
{
    const int b = blockIdx.x;
    const int j = threadIdx.x;
    const float* v = g_vals + (size_t)b * CTXN * DM + j;
    float s = 0.f;
    #pragma unroll 8
    for (int c = 0; c < CTXN; c++) s += v[(size_t)c * DM];
    g_ctx[(size_t)b * DM + j] = s;
}

// ============================================================
// Final (unchanged)
// ============================================================
__global__ void __launch_bounds__(128) final_kernel(
    const float* __restrict__ pg, const float* __restrict__ pb,
    const float* __restrict__ pW1, const float* __restrict__ pb1,
    const float* __restrict__ pW2, const float* __restrict__ pb2,
    const float* __restrict__ hg, const float* __restrict__ hb,
    const float* __restrict__ Wh, const float* __restrict__ bh,
    float* __restrict__ out)
{
    __shared__ float s_x[16][DM];
    __shared__ float s_ln[16][DM];
    __shared__ float s_h[16][DB];
    const int tid = threadIdx.x, lane = tid & 31, wid = tid >> 5;
    const int row0 = blockIdx.x * 16;

    #pragma unroll
    for (int r = 0; r < 16; r++)
        s_x[r][tid] = g_xb[(size_t)(row0 + r) * DM + tid]
                    + g_ctx[(size_t)(row0 + r) * DM + tid];
    __syncthreads();
    for (int r = wid; r < 16; r += 4) {
        float v0 = s_x[r][lane], v1 = s_x[r][lane + 32],
              v2 = s_x[r][lane + 64], v3 = s_x[r][lane + 96];
        float s = v0 + v1 + v2 + v3;
        #pragma unroll
        for (int o = 16; o; o >>= 1) s += __shfl_xor_sync(0xffffffffu, s, o);
        float mu = s * (1.f / 128.f);
        float d0 = v0 - mu, d1 = v1 - mu, d2 = v2 - mu, d3 = v3 - mu;
        float q = d0 * d0 + d1 * d1 + d2 * d2 + d3 * d3;
        #pragma unroll
        for (int o = 16; o; o >>= 1) q += __shfl_xor_sync(0xffffffffu, q, o);
        float rstd = rsqrtf(q * (1.f / 128.f) + 1e-5f);
        s_ln[r][lane]      = d0 * rstd * __ldg(&pg[lane])      + __ldg(&pb[lane]);
        s_ln[r][lane + 32] = d1 * rstd * __ldg(&pg[lane + 32]) + __ldg(&pb[lane + 32]);
        s_ln[r][lane + 64] = d2 * rstd * __ldg(&pg[lane + 64]) + __ldg(&pb[lane + 64]);
        s_ln[r][lane + 96] = d3 * rstd * __ldg(&pg[lane + 96]) + __ldg(&pb[lane + 96]);
    }
    __syncthreads();
    {
        ull a0[16], a1[16];
        float bb0 = __ldg(&pb1[tid]), bb1 = __ldg(&pb1[tid + 128]);
        #pragma unroll
        for (int r = 0; r < 16; r++) { a0[r] = pk(bb0, 0.f); a1[r] = pk(bb1, 0.f); }
        const ulonglong2* w40 = reinterpret_cast<const ulonglong2*>(pW1 + tid * DM);
        const ulonglong2* w41 = reinterpret_cast<const ulonglong2*>(pW1 + (tid + 128) * DM);
        #pragma unroll 4
        for (int jj = 0; jj < DM / 4; jj++) {
            ulonglong2 w0 = w40[jj], w1 = w41[jj];
            #pragma unroll
            for (int r = 0; r < 16; r++) {
                ulonglong2 s = *reinterpret_cast<const ulonglong2*>(&s_ln[r][jj * 4]);
                fma2(a0[r], w0.x, s.x); fma2(a0[r], w0.y, s.y);
                fma2(a1[r], w1.x, s.x); fma2(a1[r], w1.y, s.y);
            }
        }
        #pragma unroll
        for (int r = 0; r < 16; r++) {
            s_h[r][tid]       = fmaxf(fsum2(a0[r]), 0.f);
            s_h[r][tid + 128] = fmaxf(fsum2(a1[r]), 0.f);
        }
    }
    __syncthreads();
    {
        ull acc[16];
        float b2v = __ldg(&pb2[tid]);
        #pragma unroll
        for (int r = 0; r < 16; r++) acc[r] = pk(b2v, 0.f);
        const ulonglong2* w4 = reinterpret_cast<const ulonglong2*>(pW2 + tid * DB);
        #pragma unroll 2
        for (int jj = 0; jj < DB / 4; jj++) {
            ulonglong2 w = w4[jj];
            #pragma unroll
            for (int r = 0; r < 16; r++) {
                ulonglong2 s = *reinterpret_cast<const ulonglong2*>(&s_h[r][jj * 4]);
                fma2(acc[r], w.x, s.x); fma2(acc[r], w.y, s.y);
            }
        }
        #pragma unroll
        for (int r = 0; r < 16; r++) s_x[r][tid] += fsum2(acc[r]);
    }
    __syncthreads();
    for (int r = wid; r < 16; r += 4) {
        float v0 = s_x[r][lane], v1 = s_x[r][lane + 32],
              v2 = s_x[r][lane + 64], v3 = s_x[r][lane + 96];
        float s = v0 + v1 + v2 + v3;
        #pragma unroll
        for (int o = 16; o; o >>= 1) s += __shfl_xor_sync(0xffffffffu, s, o);
        float mu = s * (1.f / 128.f);
        float d0 = v0 - mu, d1 = v1 - mu, d2 = v2 - mu, d3 = v3 - mu;
        float q = d0 * d0 + d1 * d1 + d2 * d2 + d3 * d3;
        #pragma unroll
        for (int o = 16; o; o >>= 1) q += __shfl_xor_sync(0xffffffffu, q, o);
        float rstd = rsqrtf(q * (1.f / 128.f) + 1e-5f);
        s_ln[r][lane]      = fmaxf(d0 * rstd * __ldg(&hg[lane])      + __ldg(&hb[lane]), 0.f);
        s_ln[r][lane + 32] = fmaxf(d1 * rstd * __ldg(&hg[lane + 32]) + __ldg(&hb[lane + 32]), 0.f);
        s_ln[r][lane + 64] = fmaxf(d2 * rstd * __ldg(&hg[lane + 64]) + __ldg(&hb[lane + 64]), 0.f);
        s_ln[r][lane + 96] = fmaxf(d3 * rstd * __ldg(&hg[lane + 96]) + __ldg(&hb[lane + 96]), 0.f);
    }
    __syncthreads();
    for (int r = wid; r < 16; r += 4) {
        float p0 = 0.f, p1 = 0.f;
        #pragma unroll
        for (int q = 0; q < 4; q++) {
            float v = s_ln[r][lane + 32 * q];
            p0 += v * __ldg(&Wh[lane + 32 * q]);
            p1 += v * __ldg(&Wh[128 + lane + 32 * q]);
        }
        #pragma unroll
        for (int o = 16; o; o >>= 1) {
            p0 += __shfl_xor_sync(0xffffffffu, p0, o);
            p1 += __shfl_xor_sync(0xffffffffu, p1, o);
        }
        if (lane == 0) {
            out[(row0 + r) * 2 + 0] = p0 + __ldg(&bh[0]);
            out[(row0 + r) * 2 + 1] = p1 + __ldg(&bh[1]);
        }
    }
}

// ============================================================
extern "C" void kernel_launch(void* const* d_in, const int* in_sizes, int n_in,
                              void* d_out, int out_size)
{
    const float* x_num  = (const float*)d_in[0];
    const float* cand_x = (const float*)d_in[1];
    const float* cand_y = (const float*)d_in[2];
    const float* W_in   = (const float*)d_in[3];
    const float* b_in   = (const float*)d_in[4];
    const float* eW1    = (const float*)d_in[5];
    const float* eb1    = (const float*)d_in[6];
    const float* eW2    = (const float*)d_in[7];
    const float* eb2    = (const float*)d_in[8];
    const float* mg     = (const float*)d_in[9];
    const float* mb     = (const float*)d_in[10];
    const float* Wk     = (const float*)d_in[11];
    const float* bk     = (const float*)d_in[12];
    const float* w_le   = (const float*)d_in[13];
    const float* b_le   = (const float*)d_in[14];
    const float* Wt1    = (const float*)d_in[15];
    const float* bt1    = (const float*)d_in[16];
    const float* Wt2    = (const float*)d_in[17];
    const float* pg     = (const float*)d_in[18];
    const float* pb     = (const float*)d_in[19];
    const float* pW1    = (const float*)d_in[20];
    const float* pb1    = (const float*)d_in[21];
    const float* pW2    = (const float*)d_in[22];
    const float* pb2    = (const float*)d_in[23];
    const float* hg     = (const float*)d_in[24];
    const float* hb     = (const float*)d_in[25];
    const float* Wh     = (const float*)d_in[26];
    const float* bh     = (const float*)d_in[27];
    float* out = (float*)d_out;

    cudaFuncSetAttribute(encode_tc_kernel,
                         cudaFuncAttributeMaxDynamicSharedMemorySize, ENC_SMEM);
    cudaFuncSetAttribute(sims_mma_kernel,
                         cudaFuncAttributeMaxDynamicSharedMemorySize, SIMS_SMEM);
    cudaFuncSetAttribute(topk_kernel,
                         cudaFuncAttributeMaxDynamicSharedMemorySize, TOPK_SMEM);
    cudaFuncSetAttribute(ctx_mma1_kernel,
                         cudaFuncAttributeMaxDynamicSharedMemorySize, SIMS_SMEM);
    cudaFuncSetAttribute(ctx_mma2_kernel,
                         cudaFuncAttributeMaxDynamicSharedMemorySize, SIMS_SMEM);

    prep_kernel<<<(DB * DM + 255) / 256, 256>>>(Wt1, Wt2, W_in, eW1, eW2, Wk);
    encode_tc_kernel<<<ENC_GRID, 256, ENC_SMEM>>>(cand_x, x_num,
        b_in, eb1, eb2, mg, mb, bk);
    sims_mma_kernel<<<dim3(NTILES, NBATCH / BM), 256, SIMS_SMEM>>>();
    topk_kernel<<<NBATCH, 256, TOPK_SMEM>>>();
    ctx_mma1_kernel<<<dim3(DB / BN, NP / BM), 256, SIMS_SMEM>>>(bt1);
    ctx_mma2_kernel<<<dim3(1, NP / BM), 256, SIMS_SMEM>>>(cand_y, w_le, b_le);
    ctx_reduce_kernel<<<NBATCH, 128>>>();
    final_kernel<<<NBATCH / 16, 128>>>(pg, pb, pW1, pb1, pW2, pb2, hg, hb, Wh, bh, out);
}

// round 17
// speedup vs baseline: 1.0078x; 1.0038x over previous
#include <cuda_runtime.h>
#include <cuda_bf16.h>
#include <math.h>
#include <stdint.h>

#define DM 128
#define DB 256
#define NN 64
#define NC 100000
#define NBATCH 1024
#define CTXN 96
#define NP (NBATCH * CTXN)            // 98304 (b,c) pairs

// mma tiling
#define BM 128
#define BN 128
#define BK 64
#define ASTR 72   // BK + 8 pad (bf16 elems)
#define NTILES ((NC + BN - 1) / BN)   // 782
#define SIMS_SMEM (4 * BM * ASTR * 2) // Ah,Al,Bh,Bl = 73728 B

// encoder tiling
#define XSTR 136                      // 128 + 8 pad
#define ENCBLK 782                    // ceil(NC/128)
#define ENC_GRID (ENCBLK + NBATCH / 128)
#define ENC_SMEM ((2 * 128 * XSTR + 4 * 128 * ASTR) * 2)  // 143360 B

// topk block-max select
#define NBLKS (NC / 32)               // 3125
#define BSTR 3136
#define BCAP 128
#define TOPK_SMEM ((3136 + 4096 + 4096 + 4096 + 4096 + BCAP) * 4)  // 78592 B

// -------- scratch (device globals; no runtime allocation) --------
__device__ float g_cand_k[(size_t)NC * DM];   // 51.2 MB
__device__ float g_cand_cn[NC];
__device__ float g_xb[NBATCH * DM];
__device__ float g_kb[NBATCH * DM];
__device__ float g_sims[(size_t)NBATCH * NC]; // 409.6 MB
__device__ float g_bmax[(size_t)NBATCH * BSTR]; // 12.8 MB
__device__ int   g_tidx[NP];
__device__ float g_probs[NP];
__device__ float g_ctx[NBATCH * DM];
__device__ float g_vals[(size_t)NP * DM];                  // 50.3 MB
// bf16 hi/lo splits (batch side pre-scaled by 2)
__device__ __nv_bfloat16 g_kb_hi[NBATCH * DM];
__device__ __nv_bfloat16 g_kb_lo[NBATCH * DM];
__device__ __nv_bfloat16 g_ck_hi[(size_t)NC * DM];
__device__ __nv_bfloat16 g_ck_lo[(size_t)NC * DM];
// weight splits
__device__ __nv_bfloat16 g_wt1_hi[DB * DM], g_wt1_lo[DB * DM];
__device__ __nv_bfloat16 g_wt2_hi[DM * DB], g_wt2_lo[DM * DB];
__device__ __nv_bfloat16 g_win_hi[DM * NN], g_win_lo[DM * NN];
__device__ __nv_bfloat16 g_w1_hi[DB * DM],  g_w1_lo[DB * DM];
__device__ __nv_bfloat16 g_w2_hi[DM * DB],  g_w2_lo[DM * DB];
__device__ __nv_bfloat16 g_wk_hi[DM * DM],  g_wk_lo[DM * DM];
// T-network hidden activations
__device__ __nv_bfloat16 g_h_hi[(size_t)NP * DB];          // 50.3 MB
__device__ __nv_bfloat16 g_h_lo[(size_t)NP * DB];          // 50.3 MB

typedef unsigned long long ull;

// ---- packed f32x2 helpers (final kernel) ----
__device__ __forceinline__ void fma2(ull& d, ull a, ull b) {
    asm("fma.rn.f32x2 %0, %1, %2, %0;" : "+l"(d) : "l"(a), "l"(b));
}
__device__ __forceinline__ ull pk(float x, float y) {
    ull r; asm("mov.b64 %0, {%1, %2};" : "=l"(r) : "f"(x), "f"(y)); return r;
}
__device__ __forceinline__ float fsum2(ull v) {
    float x, y; asm("mov.b64 {%0, %1}, %2;" : "=f"(x), "=f"(y) : "l"(v)); return x + y;
}

__device__ __forceinline__ uint32_t smem_u32(const void* p) {
    uint32_t a;
    asm("{ .reg .u64 t; cvta.to.shared.u64 t, %1; cvt.u32.u64 %0, t; }"
        : "=r"(a) : "l"(p));
    return a;
}
__device__ __forceinline__ void ldsm4(uint32_t& r0, uint32_t& r1,
                                      uint32_t& r2, uint32_t& r3, uint32_t addr) {
    asm volatile("ldmatrix.sync.aligned.m8n8.x4.shared.b16 {%0,%1,%2,%3}, [%4];"
        : "=r"(r0), "=r"(r1), "=r"(r2), "=r"(r3) : "r"(addr));
}
__device__ __forceinline__ void mma16816(float* c, uint32_t a0, uint32_t a1,
                                         uint32_t a2, uint32_t a3,
                                         uint32_t b0, uint32_t b1) {
    asm volatile(
        "mma.sync.aligned.m16n8k16.row.col.f32.bf16.bf16.f32 "
        "{%0,%1,%2,%3}, {%4,%5,%6,%7}, {%8,%9}, {%0,%1,%2,%3};"
        : "+f"(c[0]), "+f"(c[1]), "+f"(c[2]), "+f"(c[3])
        : "r"(a0), "r"(a1), "r"(a2), "r"(a3), "r"(b0), "r"(b1));
}
__device__ __forceinline__ void split_bf16(float v, __nv_bfloat16& h, __nv_bfloat16& l) {
    h = __float2bfloat16(v);
    l = __float2bfloat16(v - __bfloat162float(h));
}
__device__ __forceinline__ float bf2f(__nv_bfloat16 v) { return __bfloat162float(v); }

// ============================================================
// prep: split all fp32 weights into bf16 hi/lo
// ============================================================
__global__ void __launch_bounds__(256) prep_kernel(
    const float* __restrict__ Wt1, const float* __restrict__ Wt2,
    const float* __restrict__ W_in, const float* __restrict__ W1,
    const float* __restrict__ W2, const float* __restrict__ Wk)
{
    int i = blockIdx.x * 256 + threadIdx.x;
    __nv_bfloat16 h, l;
    if (i < DB * DM) {
        split_bf16(Wt1[i], h, l); g_wt1_hi[i] = h; g_wt1_lo[i] = l;
        split_bf16(Wt2[i], h, l); g_wt2_hi[i] = h; g_wt2_lo[i] = l;
        split_bf16(W1[i],  h, l); g_w1_hi[i]  = h; g_w1_lo[i]  = l;
        split_bf16(W2[i],  h, l); g_w2_hi[i]  = h; g_w2_lo[i]  = l;
    }
    if (i < DM * NN) { split_bf16(W_in[i], h, l); g_win_hi[i] = h; g_win_lo[i] = l; }
    if (i < DM * DM) { split_bf16(Wk[i],  h, l); g_wk_hi[i]  = h; g_wk_lo[i]  = l; }
}

// ============================================================
// Tensor-core encoder (unchanged from R12)
// ============================================================
__global__ void __launch_bounds__(256) encode_tc_kernel(
    const float* __restrict__ xnum_c, const float* __restrict__ xnum_b,
    const float* __restrict__ b_in, const float* __restrict__ b1,
    const float* __restrict__ b2,
    const float* __restrict__ mg, const float* __restrict__ mb,
    const float* __restrict__ bk)
{
    extern __shared__ __nv_bfloat16 sm2[];
    __nv_bfloat16* sXh = sm2;
    __nv_bfloat16* sXl = sXh + 128 * XSTR;
    __nv_bfloat16* sAh = sXl + 128 * XSTR;
    __nv_bfloat16* sAl = sAh + 128 * ASTR;
    __nv_bfloat16* sBh = sAl + 128 * ASTR;
    __nv_bfloat16* sBl = sBh + 128 * ASTR;

    const int tid = threadIdx.x, lane = tid & 31, w = tid >> 5;
    const int wm = w & 3, wn = w >> 2;
    const bool cand = (blockIdx.x < ENCBLK);
    const int row0 = cand ? blockIdx.x * 128 : (int)(blockIdx.x - ENCBLK) * 128;
    const int nrows = cand ? min(128, NC - row0) : 128;
    const float* xnum = cand ? xnum_c : xnum_b;

    const uint32_t uXh = smem_u32(sXh), uXl = smem_u32(sXl);
    const uint32_t uAh = smem_u32(sAh), uAl = smem_u32(sAl);
    const uint32_t uBh = smem_u32(sBh), uBl = smem_u32(sBl);
    const int a_row = lane & 15, a_half = lane >> 4;
    const int b_grp = lane >> 3, b_row = lane & 7;
    const int b_nt = b_grp >> 1, b_kh = b_grp & 1;
    const int c_row = lane >> 2, c_col2 = (lane & 3) * 2;

    #pragma unroll
    for (int t = 0; t < 8; t++) {
        int idx = t * 256 + tid;
        int row = idx >> 4, q4 = (idx & 15) * 4;
        float4 v = make_float4(0.f, 0.f, 0.f, 0.f);
        if (row < nrows)
            v = *reinterpret_cast<const float4*>(&xnum[(size_t)(row0 + row) * NN + q4]);
        float vv[4] = {v.x, v.y, v.z, v.w};
        __nv_bfloat16 hh[4], ll[4];
        #pragma unroll
        for (int e = 0; e < 4; e++) split_bf16(vv[e], hh[e], ll[e]);
        *reinterpret_cast<ull*>(&sAh[row * ASTR + q4]) = *reinterpret_cast<ull*>(hh);
        *reinterpret_cast<ull*>(&sAl[row * ASTR + q4]) = *reinterpret_cast<ull*>(ll);
    }
    #pragma unroll
    for (int t = 0; t < 4; t++) {
        int idx = t * 256 + tid;
        int row = idx >> 3, c8 = (idx & 7) * 8;
        *reinterpret_cast<float4*>(&sBh[row * ASTR + c8]) =
            *reinterpret_cast<const float4*>(&g_win_hi[row * NN + c8]);
        *reinterpret_cast<float4*>(&sBl[row * ASTR + c8]) =
            *reinterpret_cast<const float4*>(&g_win_lo[row * NN + c8]);
    }
    __syncthreads();

    float c[2][8][4];
    #pragma unroll
    for (int i = 0; i < 2; i++)
        #pragma unroll
        for (int j = 0; j < 8; j++)
            #pragma unroll
            for (int q = 0; q < 4; q++) c[i][j][q] = 0.f;

    #pragma unroll
    for (int ks = 0; ks < 4; ks++) {
        const int kb = ks * 16;
        uint32_t ah[2][4], al[2][4];
        #pragma unroll
        for (int mi = 0; mi < 2; mi++) {
            uint32_t off = (uint32_t)((wm * 32 + mi * 16 + a_row) * ASTR + kb + a_half * 8) * 2;
            ldsm4(ah[mi][0], ah[mi][1], ah[mi][2], ah[mi][3], uAh + off);
            ldsm4(al[mi][0], al[mi][1], al[mi][2], al[mi][3], uAl + off);
        }
        uint32_t bh[8][2], bl[8][2];
        #pragma unroll
        for (int nq = 0; nq < 4; nq++) {
            uint32_t off = (uint32_t)((wn * 64 + nq * 16 + b_nt * 8 + b_row) * ASTR + kb + b_kh * 8) * 2;
            uint32_t r0, r1, r2, r3;
            ldsm4(r0, r1, r2, r3, uBh + off);
            bh[nq * 2][0] = r0; bh[nq * 2][1] = r1;
            bh[nq * 2 + 1][0] = r2; bh[nq * 2 + 1][1] = r3;
            ldsm4(r0, r1, r2, r3, uBl + off);
            bl[nq * 2][0] = r0; bl[nq * 2][1] = r1;
            bl[nq * 2 + 1][0] = r2; bl[nq * 2 + 1][1] = r3;
        }
        #pragma unroll
        for (int mi = 0; mi < 2; mi++)
            #pragma unroll
            for (int ni = 0; ni < 8; ni++) {
                mma16816(c[mi][ni], ah[mi][0], ah[mi][1], ah[mi][2], ah[mi][3], bh[ni][0], bh[ni][1]);
                mma16816(c[mi][ni], ah[mi][0], ah[mi][1], ah[mi][2], ah[mi][3], bl[ni][0], bl[ni][1]);
                mma16816(c[mi][ni], al[mi][0], al[mi][1], al[mi][2], al[mi][3], bh[ni][0], bh[ni][1]);
            }
    }
    #pragma unroll
    for (int mi = 0; mi < 2; mi++) {
        #pragma unroll
        for (int ni = 0; ni < 8; ni++) {
            int col = wn * 64 + ni * 8 + c_col2;
            int row = wm * 32 + mi * 16 + c_row;
            float bb0 = __ldg(&b_in[col]), bb1 = __ldg(&b_in[col + 1]);
            #pragma unroll
            for (int half = 0; half < 2; half++) {
                int r = row + half * 8;
                float x0 = c[mi][ni][half * 2]     + bb0;
                float x1 = c[mi][ni][half * 2 + 1] + bb1;
                __nv_bfloat16 h0, l0, h1, l1;
                split_bf16(x0, h0, l0); split_bf16(x1, h1, l1);
                __nv_bfloat162 ph; ph.x = h0; ph.y = h1;
                __nv_bfloat162 pl; pl.x = l0; pl.y = l1;
                *reinterpret_cast<__nv_bfloat162*>(&sXh[r * XSTR + col]) = ph;
                *reinterpret_cast<__nv_bfloat162*>(&sXl[r * XSTR + col]) = pl;
            }
        }
    }

    float c3[2][8][4];
    #pragma unroll
    for (int i = 0; i < 2; i++)
        #pragma unroll
        for (int j = 0; j < 8; j++)
            #pragma unroll
            for (int q = 0; q < 4; q++) c3[i][j][q] = 0.f;

    #pragma unroll 1
    for (int hc = 0; hc < 4; hc++) {
        __syncthreads();
        #pragma unroll
        for (int t = 0; t < 4; t++) {
            int idx = t * 256 + tid;
            int row = idx >> 4, c8 = (idx & 15) * 8;
            *reinterpret_cast<float4*>(&sBh[row * XSTR + c8]) =
                *reinterpret_cast<const float4*>(&g_w1_hi[(hc * 64 + row) * DM + c8]);
            *reinterpret_cast<float4*>(&sBl[row * XSTR + c8]) =
                *reinterpret_cast<const float4*>(&g_w1_lo[(hc * 64 + row) * DM + c8]);
        }
        __syncthreads();
        float c2[2][4][4];
        #pragma unroll
        for (int i = 0; i < 2; i++)
            #pragma unroll
            for (int j = 0; j < 4; j++)
                #pragma unroll
                for (int q = 0; q < 4; q++) c2[i][j][q] = 0.f;
        #pragma unroll
        for (int ks = 0; ks < 8; ks++) {
            const int kb = ks * 16;
            uint32_t ah[2][4], al[2][4];
            #pragma unroll
            for (int mi = 0; mi < 2; mi++) {
                uint32_t off = (uint32_t)((wm * 32 + mi * 16 + a_row) * XSTR + kb + a_half * 8) * 2;
                ldsm4(ah[mi][0], ah[mi][1], ah[mi][2], ah[mi][3], uXh + off);
                ldsm4(al[mi][0], al[mi][1], al[mi][2], al[mi][3], uXl + off);
            }
            uint32_t bh[4][2], bl[4][2];
            #pragma unroll
            for (int nq = 0; nq < 2; nq++) {
                uint32_t off = (uint32_t)((wn * 32 + nq * 16 + b_nt * 8 + b_row) * XSTR + kb + b_kh * 8) * 2;
                uint32_t r0, r1, r2, r3;
                ldsm4(r0, r1, r2, r3, uBh + off);
                bh[nq * 2][0] = r0; bh[nq * 2][1] = r1;
                bh[nq * 2 + 1][0] = r2; bh[nq * 2 + 1][1] = r3;
                ldsm4(r0, r1, r2, r3, uBl + off);
                bl[nq * 2][0] = r0; bl[nq * 2][1] = r1;
                bl[nq * 2 + 1][0] = r2; bl[nq * 2 + 1][1] = r3;
            }
            #pragma unroll
            for (int mi = 0; mi < 2; mi++)
                #pragma unroll
                for (int ni = 0; ni < 4; ni++) {
                    mma16816(c2[mi][ni], ah[mi][0], ah[mi][1], ah[mi][2], ah[mi][3], bh[ni][0], bh[ni][1]);
                    mma16816(c2[mi][ni], ah[mi][0], ah[mi][1], ah[mi][2], ah[mi][3], bl[ni][0], bl[ni][1]);
                    mma16816(c2[mi][ni], al[mi][0], al[mi][1], al[mi][2], al[mi][3], bh[ni][0], bh[ni][1]);
                }
        }
        #pragma unroll
        for (int mi = 0; mi < 2; mi++) {
            #pragma unroll
            for (int ni = 0; ni < 4; ni++) {
                int col = wn * 32 + ni * 8 + c_col2;
                int row = wm * 32 + mi * 16 + c_row;
                float bb0 = __ldg(&b1[hc * 64 + col]), bb1 = __ldg(&b1[hc * 64 + col + 1]);
                #pragma unroll
                for (int half = 0; half < 2; half++) {
                    int r = row + half * 8;
                    float h0 = fmaxf(c2[mi][ni][half * 2]     + bb0, 0.f);
                    float h1 = fmaxf(c2[mi][ni][half * 2 + 1] + bb1, 0.f);
                    __nv_bfloat16 hh0, ll0, hh1, ll1;
                    split_bf16(h0, hh0, ll0); split_bf16(h1, hh1, ll1);
                    __nv_bfloat162 ph; ph.x = hh0; ph.y = hh1;
                    __nv_bfloat162 pl; pl.x = ll0; pl.y = ll1;
                    *reinterpret_cast<__nv_bfloat162*>(&sAh[r * ASTR + col]) = ph;
                    *reinterpret_cast<__nv_bfloat162*>(&sAl[r * ASTR + col]) = pl;
                }
            }
        }
        __syncthreads();
        #pragma unroll
        for (int t = 0; t < 4; t++) {
            int idx = t * 256 + tid;
            int row = idx >> 3, c8 = (idx & 7) * 8;
            *reinterpret_cast<float4*>(&sBh[row * ASTR + c8]) =
                *reinterpret_cast<const float4*>(&g_w2_hi[row * DB + hc * 64 + c8]);
            *reinterpret_cast<float4*>(&sBl[row * ASTR + c8]) =
                *reinterpret_cast<const float4*>(&g_w2_lo[row * DB + hc * 64 + c8]);
        }
        __syncthreads();
        #pragma unroll
        for (int ks = 0; ks < 4; ks++) {
            const int kb = ks * 16;
            uint32_t ah[2][4], al[2][4];
            #pragma unroll
            for (int mi = 0; mi < 2; mi++) {
                uint32_t off = (uint32_t)((wm * 32 + mi * 16 + a_row) * ASTR + kb + a_half * 8) * 2;
                ldsm4(ah[mi][0], ah[mi][1], ah[mi][2], ah[mi][3], uAh + off);
                ldsm4(al[mi][0], al[mi][1], al[mi][2], al[mi][3], uAl + off);
            }
            uint32_t bh[8][2], bl[8][2];
            #pragma unroll
            for (int nq = 0; nq < 4; nq++) {
                uint32_t off = (uint32_t)((wn * 64 + nq * 16 + b_nt * 8 + b_row) * ASTR + kb + b_kh * 8) * 2;
                uint32_t r0, r1, r2, r3;
                ldsm4(r0, r1, r2, r3, uBh + off);
                bh[nq * 2][0] = r0; bh[nq * 2][1] = r1;
                bh[nq * 2 + 1][0] = r2; bh[nq * 2 + 1][1] = r3;
                ldsm4(r0, r1, r2, r3, uBl + off);
                bl[nq * 2][0] = r0; bl[nq * 2][1] = r1;
                bl[nq * 2 + 1][0] = r2; bl[nq * 2 + 1][1] = r3;
            }
            #pragma unroll
            for (int mi = 0; mi < 2; mi++)
                #pragma unroll
                for (int ni = 0; ni < 8; ni++) {
                    mma16816(c3[mi][ni], ah[mi][0], ah[mi][1], ah[mi][2], ah[mi][3], bh[ni][0], bh[ni][1]);
                    mma16816(c3[mi][ni], ah[mi][0], ah[mi][1], ah[mi][2], ah[mi][3], bl[ni][0], bl[ni][1]);
                    mma16816(c3[mi][ni], al[mi][0], al[mi][1], al[mi][2], al[mi][3], bh[ni][0], bh[ni][1]);
                }
        }
    }

    #pragma unroll
    for (int mi = 0; mi < 2; mi++) {
        #pragma unroll
        for (int ni = 0; ni < 8; ni++) {
            int col = wn * 64 + ni * 8 + c_col2;
            int row = wm * 32 + mi * 16 + c_row;
            float bb0 = __ldg(&b2[col]), bb1 = __ldg(&b2[col + 1]);
            #pragma unroll
            for (int half = 0; half < 2; half++) {
                int r = row + half * 8;
                __nv_bfloat162 ph = *reinterpret_cast<__nv_bfloat162*>(&sXh[r * XSTR + col]);
                __nv_bfloat162 pl = *reinterpret_cast<__nv_bfloat162*>(&sXl[r * XSTR + col]);
                float x0 = bf2f(ph.x) + bf2f(pl.x) + c3[mi][ni][half * 2]     + bb0;
                float x1 = bf2f(ph.y) + bf2f(pl.y) + c3[mi][ni][half * 2 + 1] + bb1;
                if (!cand)
                    *reinterpret_cast<float2*>(&g_xb[(size_t)(row0 + r) * DM + col]) =
                        make_float2(x0, x1);
                __nv_bfloat16 h0, l0, h1, l1;
                split_bf16(x0, h0, l0); split_bf16(x1, h1, l1);
                ph.x = h0; ph.y = h1; pl.x = l0; pl.y = l1;
                *reinterpret_cast<__nv_bfloat162*>(&sXh[r * XSTR + col]) = ph;
                *reinterpret_cast<__nv_bfloat162*>(&sXl[r * XSTR + col]) = pl;
            }
        }
    }
    __syncthreads();

    for (int r = w; r < 128; r += 8) {
        float v[4];
        #pragma unroll
        for (int i = 0; i < 4; i++) {
            int cc = lane + 32 * i;
            v[i] = bf2f(sXh[r * XSTR + cc]) + bf2f(sXl[r * XSTR + cc]);
        }
        float s = v[0] + v[1] + v[2] + v[3];
        #pragma unroll
        for (int o = 16; o; o >>= 1) s += __shfl_xor_sync(0xffffffffu, s, o);
        float mu = s * (1.f / 128.f);
        float d[4] = {v[0] - mu, v[1] - mu, v[2] - mu, v[3] - mu};
        float q = d[0] * d[0] + d[1] * d[1] + d[2] * d[2] + d[3] * d[3];
        #pragma unroll
        for (int o = 16; o; o >>= 1) q += __shfl_xor_sync(0xffffffffu, q, o);
        float rstd = rsqrtf(q * (1.f / 128.f) + 1e-5f);
        #pragma unroll
        for (int i = 0; i < 4; i++) {
            int cc = lane + 32 * i;
            float ln = d[i] * rstd * __ldg(&mg[cc]) + __ldg(&mb[cc]);
            __nv_bfloat16 h, l; split_bf16(ln, h, l);
            sXh[r * XSTR + cc] = h;
            sXl[r * XSTR + cc] = l;
        }
    }

    #pragma unroll
    for (int i = 0; i < 2; i++)
        #pragma unroll
        for (int j = 0; j < 8; j++)
            #pragma unroll
            for (int q = 0; q < 4; q++) c[i][j][q] = 0.f;
    #pragma unroll 1
    for (int kc2 = 0; kc2 < 2; kc2++) {
        __syncthreads();
        #pragma unroll
        for (int t = 0; t < 4; t++) {
            int idx = t * 256 + tid;
            int row = idx >> 3, c8 = (idx & 7) * 8;
            *reinterpret_cast<float4*>(&sBh[row * ASTR + c8]) =
                *reinterpret_cast<const float4*>(&g_wk_hi[row * DM + kc2 * 64 + c8]);
            *reinterpret_cast<float4*>(&sBl[row * ASTR + c8]) =
                *reinterpret_cast<const float4*>(&g_wk_lo[row * DM + kc2 * 64 + c8]);
        }
        __syncthreads();
        #pragma unroll
        for (int ks = 0; ks < 4; ks++) {
            const int kb = ks * 16;
            uint32_t ah[2][4], al[2][4];
            #pragma unroll
            for (int mi = 0; mi < 2; mi++) {
                uint32_t off = (uint32_t)((wm * 32 + mi * 16 + a_row) * XSTR + kc2 * 64 + kb + a_half * 8) * 2;
                ldsm4(ah[mi][0], ah[mi][1], ah[mi][2], ah[mi][3], uXh + off);
                ldsm4(al[mi][0], al[mi][1], al[mi][2], al[mi][3], uXl + off);
            }
            uint32_t bh[8][2], bl[8][2];
            #pragma unroll
            for (int nq = 0; nq < 4; nq++) {
                uint32_t off = (uint32_t)((wn * 64 + nq * 16 + b_nt * 8 + b_row) * ASTR + kb + b_kh * 8) * 2;
                uint32_t r0, r1, r2, r3;
                ldsm4(r0, r1, r2, r3, uBh + off);
                bh[nq * 2][0] = r0; bh[nq * 2][1] = r1;
                bh[nq * 2 + 1][0] = r2; bh[nq * 2 + 1][1] = r3;
                ldsm4(r0, r1, r2, r3, uBl + off);
                bl[nq * 2][0] = r0; bl[nq * 2][1] = r1;
                bl[nq * 2 + 1][0] = r2; bl[nq * 2 + 1][1] = r3;
            }
            #pragma unroll
            for (int mi = 0; mi < 2; mi++)
                #pragma unroll
                for (int ni = 0; ni < 8; ni++) {
                    mma16816(c[mi][ni], ah[mi][0], ah[mi][1], ah[mi][2], ah[mi][3], bh[ni][0], bh[ni][1]);
                    mma16816(c[mi][ni], ah[mi][0], ah[mi][1], ah[mi][2], ah[mi][3], bl[ni][0], bl[ni][1]);
                    mma16816(c[mi][ni], al[mi][0], al[mi][1], al[mi][2], al[mi][3], bh[ni][0], bh[ni][1]);
                }
        }
    }
    __syncthreads();
    #pragma unroll
    for (int mi = 0; mi < 2; mi++) {
        #pragma unroll
        for (int ni = 0; ni < 8; ni++) {
            int col = wn * 64 + ni * 8 + c_col2;
            int row = wm * 32 + mi * 16 + c_row;
            float bb0 = __ldg(&bk[col]), bb1 = __ldg(&bk[col + 1]);
            #pragma unroll
            for (int half = 0; half < 2; half++) {
                int r = row + half * 8;
                float k0 = c[mi][ni][half * 2]     + bb0;
                float k1 = c[mi][ni][half * 2 + 1] + bb1;
                __nv_bfloat16 h0, l0, h1, l1;
                split_bf16(k0, h0, l0); split_bf16(k1, h1, l1);
                __nv_bfloat162 ph; ph.x = h0; ph.y = h1;
                __nv_bfloat162 pl; pl.x = l0; pl.y = l1;
                *reinterpret_cast<__nv_bfloat162*>(&sXh[r * XSTR + col]) = ph;
                *reinterpret_cast<__nv_bfloat162*>(&sXl[r * XSTR + col]) = pl;
            }
        }
    }
    __syncthreads();

    {
        const float scale = cand ? 1.f : 2.f;
        float* out_k = cand ? g_cand_k : g_kb;
        __nv_bfloat16* out_hi = cand ? g_ck_hi : g_kb_hi;
        __nv_bfloat16* out_lo = cand ? g_ck_lo : g_kb_lo;
        #pragma unroll
        for (int t = 0; t < 16; t++) {
            int idx = t * 256 + tid;
            int row = idx >> 5, q4 = (idx & 31) * 4;
            if (row < nrows) {
                ull uh = *reinterpret_cast<ull*>(&sXh[row * XSTR + q4]);
                ull ul = *reinterpret_cast<ull*>(&sXl[row * XSTR + q4]);
                __nv_bfloat16* hp = reinterpret_cast<__nv_bfloat16*>(&uh);
                __nv_bfloat16* lp = reinterpret_cast<__nv_bfloat16*>(&ul);
                float kv[4];
                __nv_bfloat16 oh[4], ol[4];
                #pragma unroll
                for (int e = 0; e < 4; e++) {
                    kv[e] = bf2f(hp[e]) + bf2f(lp[e]);
                    split_bf16(scale * kv[e], oh[e], ol[e]);
                }
                size_t base = (size_t)(row0 + row) * DM + q4;
                *reinterpret_cast<float4*>(&out_k[base]) =
                    make_float4(kv[0], kv[1], kv[2], kv[3]);
                *reinterpret_cast<ull*>(&out_hi[base]) = *reinterpret_cast<ull*>(oh);
                *reinterpret_cast<ull*>(&out_lo[base]) = *reinterpret_cast<ull*>(ol);
            }
        }
    }
    if (cand) {
        for (int r = w; r < 128; r += 8) {
            float q = 0.f;
            #pragma unroll
            for (int i = 0; i < 4; i++) {
                int cc = lane + 32 * i;
                float v = bf2f(sXh[r * XSTR + cc]) + bf2f(sXl[r * XSTR + cc]);
                q += v * v;
            }
            #pragma unroll
            for (int o = 16; o; o >>= 1) q += __shfl_xor_sync(0xffffffffu, q, o);
            if (lane == 0 && r < nrows) g_cand_cn[row0 + r] = q;
        }
    }
}

// ============================================================
// sims via mma.sync bf16 split GEMM; epilogue also emits
// per-(row, 32-col-block) maxima into g_bmax.
// ============================================================
__global__ void __launch_bounds__(256) sims_mma_kernel()
{
    extern __shared__ __nv_bfloat16 sm[];
    __nv_bfloat16* sAh = sm;
    __nv_bfloat16* sAl = sAh + BM * ASTR;
    __nv_bfloat16* sBh = sAl + BM * ASTR;
    __nv_bfloat16* sBl = sBh + BM * ASTR;

    const int tid  = threadIdx.x;
    const int lane = tid & 31;
    const int w    = tid >> 5;
    const int wm   = w & 3;
    const int wn   = w >> 2;
    const int m0 = blockIdx.y * BM;
    const int n0 = blockIdx.x * BN;

    const uint32_t uAh = smem_u32(sAh), uAl = smem_u32(sAl);
    const uint32_t uBh = smem_u32(sBh), uBl = smem_u32(sBl);

    float c[2][8][4];
    #pragma unroll
    for (int i = 0; i < 2; i++)
        #pragma unroll
        for (int j = 0; j < 8; j++)
            #pragma unroll
            for (int q = 0; q < 4; q++) c[i][j][q] = 0.f;

    const int a_row = lane & 15, a_half = lane >> 4;
    const int b_grp = lane >> 3, b_row = lane & 7;
    const int b_nt = b_grp >> 1, b_kh = b_grp & 1;

    #pragma unroll 1
    for (int ch = 0; ch < 2; ch++) {
        const int kc = ch * BK;
        #pragma unroll
        for (int t = 0; t < 4; t++) {
            int idx = t * 256 + tid;
            int row = idx >> 3, c8 = (idx & 7) * 8;
            *reinterpret_cast<float4*>(&sAh[row * ASTR + c8]) =
                *reinterpret_cast<const float4*>(&g_kb_hi[(m0 + row) * DM + kc + c8]);
            *reinterpret_cast<float4*>(&sAl[row * ASTR + c8]) =
                *reinterpret_cast<const float4*>(&g_kb_lo[(m0 + row) * DM + kc + c8]);
        }
        #pragma unroll
        for (int t = 0; t < 4; t++) {
            int idx = t * 256 + tid;
            int row = idx >> 3, c8 = (idx & 7) * 8;
            int col = n0 + row;
            float4 vh = make_float4(0.f, 0.f, 0.f, 0.f), vl = vh;
            if (col < NC) {
                vh = *reinterpret_cast<const float4*>(&g_ck_hi[(size_t)col * DM + kc + c8]);
                vl = *reinterpret_cast<const float4*>(&g_ck_lo[(size_t)col * DM + kc + c8]);
            }
            *reinterpret_cast<float4*>(&sBh[row * ASTR + c8]) = vh;
            *reinterpret_cast<float4*>(&sBl[row * ASTR + c8]) = vl;
        }
        __syncthreads();

        #pragma unroll
        for (int ks = 0; ks < BK / 16; ks++) {
            const int kb = ks * 16;
            uint32_t ah[2][4], al[2][4];
            #pragma unroll
            for (int mi = 0; mi < 2; mi++) {
                uint32_t off = (uint32_t)((wm * 32 + mi * 16 + a_row) * ASTR + kb + a_half * 8) * 2;
                ldsm4(ah[mi][0], ah[mi][1], ah[mi][2], ah[mi][3], uAh + off);
                ldsm4(al[mi][0], al[mi][1], al[mi][2], al[mi][3], uAl + off);
            }
            uint32_t bh[8][2], bl[8][2];
            #pragma unroll
            for (int nq = 0; nq < 4; nq++) {
                uint32_t off = (uint32_t)((wn * 64 + nq * 16 + b_nt * 8 + b_row) * ASTR + kb + b_kh * 8) * 2;
                uint32_t r0, r1, r2, r3;
                ldsm4(r0, r1, r2, r3, uBh + off);
                bh[nq * 2][0] = r0; bh[nq * 2][1] = r1;
                bh[nq * 2 + 1][0] = r2; bh[nq * 2 + 1][1] = r3;
                ldsm4(r0, r1, r2, r3, uBl + off);
                bl[nq * 2][0] = r0; bl[nq * 2][1] = r1;
                bl[nq * 2 + 1][0] = r2; bl[nq * 2 + 1][1] = r3;
            }
            #pragma unroll
            for (int mi = 0; mi < 2; mi++)
                #pragma unroll
                for (int ni = 0; ni < 8; ni++) {
                    mma16816(c[mi][ni], ah[mi][0], ah[mi][1], ah[mi][2], ah[mi][3], bh[ni][0], bh[ni][1]);
                    mma16816(c[mi][ni], ah[mi][0], ah[mi][1], ah[mi][2], ah[mi][3], bl[ni][0], bl[ni][1]);
                    mma16816(c[mi][ni], al[mi][0], al[mi][1], al[mi][2], al[mi][3], bh[ni][0], bh[ni][1]);
                }
        }
        __syncthreads();
    }

    const int col_base = n0 + wn * 64 + (lane & 3) * 2;
    float2 cn[8];
    #pragma unroll
    for (int ni = 0; ni < 8; ni++) {
        int col = col_base + ni * 8;
        cn[ni].x = (col < NC) ? __ldg(&g_cand_cn[col]) : 0.f;
        cn[ni].y = (col < NC) ? __ldg(&g_cand_cn[col + 1]) : 0.f;
    }
    #pragma unroll
    for (int mi = 0; mi < 2; mi++) {
        int row = m0 + wm * 32 + mi * 16 + (lane >> 2);
        float* d0 = &g_sims[(size_t)row * NC];
        float* d1 = &g_sims[(size_t)(row + 8) * NC];
        float bmA[2] = {-3.4e38f, -3.4e38f};
        float bmB[2] = {-3.4e38f, -3.4e38f};
        #pragma unroll
        for (int ni = 0; ni < 8; ni++) {
            int col = col_base + ni * 8;
            if (col < NC) {
                float v00 = c[mi][ni][0] - cn[ni].x, v01 = c[mi][ni][1] - cn[ni].y;
                float v10 = c[mi][ni][2] - cn[ni].x, v11 = c[mi][ni][3] - cn[ni].y;
                *reinterpret_cast<float2*>(d0 + col) = make_float2(v00, v01);
                *reinterpret_cast<float2*>(d1 + col) = make_float2(v10, v11);
                int b = ni >> 2;
                bmA[b] = fmaxf(bmA[b], fmaxf(v00, v01));
                bmB[b] = fmaxf(bmB[b], fmaxf(v10, v11));
            }
        }
        #pragma unroll
        for (int b = 0; b < 2; b++) {
            float ma = bmA[b], mb2 = bmB[b];
            ma  = fmaxf(ma,  __shfl_xor_sync(0xffffffffu, ma, 1));
            ma  = fmaxf(ma,  __shfl_xor_sync(0xffffffffu, ma, 2));
            mb2 = fmaxf(mb2, __shfl_xor_sync(0xffffffffu, mb2, 1));
            mb2 = fmaxf(mb2, __shfl_xor_sync(0xffffffffu, mb2, 2));
            int cb = n0 + wn * 64 + b * 32;
            if ((lane & 3) == 0 && cb < NC) {
                int blk = cb >> 5;
                g_bmax[(size_t)row * BSTR + blk] = ma;
                g_bmax[(size_t)(row + 8) * BSTR + blk] = mb2;
            }
        }
    }
}

// ============================================================
// Block-max assisted exact top-96.
// ============================================================
__device__ __forceinline__ unsigned f2k(float f) {
    unsigned u = __float_as_uint(f);
    return (u & 0x80000000u) ? ~u : (u | 0x80000000u);
}

// exact 32-bit radix select over smem-resident keys (3 levels: 12/12/8).
// returns key T s.t. count(>T) < need <= count(>=T); *need_eq = need - count(>T)
__device__ unsigned radix_select(const unsigned* __restrict__ keys, int n, int need,
                                 unsigned* hist, unsigned* psum,
                                 int* s_bin, int* s_need, int tid, int* need_eq)
{
    // level 1: bits [31:20]
    for (int i = tid; i < 4096; i += 256) hist[i] = 0;
    __syncthreads();
    for (int i = tid; i < n; i += 256) atomicAdd(&hist[keys[i] >> 20], 1u);
    __syncthreads();
    if (tid < 128) {
        unsigned s = 0;
        for (int j = 0; j < 32; j++) s += hist[tid * 32 + j];
        psum[tid] = s;
    }
    __syncthreads();
    if (tid == 0) {
        int nd = need; unsigned cum = 0; int g = 127;
        for (; g >= 0; g--) { if (cum + psum[g] >= (unsigned)nd) break; cum += psum[g]; }
        for (int j = 31; j >= 0; j--) {
            unsigned c = hist[g * 32 + j];
            if (cum + c >= (unsigned)nd) { *s_bin = g * 32 + j; *s_need = nd - (int)cum; break; }
            cum += c;
        }
    }
    __syncthreads();
    const unsigned b1 = (unsigned)*s_bin;
    const int need1 = *s_need;
    __syncthreads();
    // level 2: bits [19:8]
    for (int i = tid; i < 4096; i += 256) hist[i] = 0;
    __syncthreads();
    for (int i = tid; i < n; i += 256) {
        unsigned k = keys[i];
        if ((k >> 20) == b1) atomicAdd(&hist[(k >> 8) & 0xFFFu], 1u);
    }
    __syncthreads();
    if (tid < 128) {
        unsigned s = 0;
        for (int j = 0; j < 32; j++) s += hist[tid * 32 + j];
        psum[tid] = s;
    }
    __syncthreads();
    if (tid == 0) {
        int nd = need1; unsigned cum = 0; int g = 127;
        for (; g >= 0; g--) { if (cum + psum[g] >= (unsigned)nd) break; cum += psum[g]; }
        for (int j = 31; j >= 0; j--) {
            unsigned c = hist[g * 32 + j];
            if (cum + c >= (unsigned)nd) { *s_bin = g * 32 + j; *s_need = nd - (int)cum; break; }
            cum += c;
        }
    }
    __syncthreads();
    const unsigned b2 = (unsigned)*s_bin;
    const int need2 = *s_need;
    const unsigned p2 = (b1 << 12) | b2;
    __syncthreads();
    // level 3: bits [7:0]
    for (int i = tid; i < 256; i += 256) hist[i] = 0;
    __syncthreads();
    for (int i = tid; i < n; i += 256) {
        unsigned k = keys[i];
        if ((k >> 8) == p2) atomicAdd(&hist[k & 0xFFu], 1u);
    }
    __syncthreads();
    if (tid == 0) {
        int nd = need2; unsigned cum = 0;
        for (int j = 255; j >= 0; j--) {
            unsigned c = hist[j];
            if (cum + c >= (unsigned)nd) { *s_bin = j; *s_need = nd - (int)cum; break; }
            cum += c;
        }
    }
    __syncthreads();
    unsigned T = (p2 << 8) | (unsigned)*s_bin;
    *need_eq = *s_need;
    __syncthreads();
    return T;
}

__global__ void __launch_bounds__(256) topk_kernel()
{
    const int row = blockIdx.x;
    const int tid = threadIdx.x;
    extern __shared__ unsigned tsm[];
    unsigned* s_keys = tsm;                      // 3136
    unsigned* hist   = s_keys + 3136;            // 4096
    float*    s_cv   = (float*)(hist + 4096);    // 4096
    int*      s_ci   = (int*)(s_cv + 4096);      // 4096
    unsigned* s_ck   = (unsigned*)(s_ci + 4096); // 4096
    int*      s_blk  = (int*)(s_ck + 4096);      // BCAP
    __shared__ unsigned psum[128];
    __shared__ int s_bin, s_need, s_nblk, s_cnt, s_eqc;
    __shared__ float s_vals[CTXN];
    __shared__ int s_ids[CTXN];
    __shared__ float s_red;

    // ---- load block-max keys
    const float* bmax = g_bmax + (size_t)row * BSTR;
    for (int i = tid; i < NBLKS; i += 256) s_keys[i] = f2k(bmax[i]);
    if (tid == 0) s_nblk = 0;
    __syncthreads();

    // ---- exact 96th-largest block max
    int dmy;
    unsigned Tb = radix_select(s_keys, NBLKS, CTXN, hist, psum, &s_bin, &s_need, tid, &dmy);

    // ---- gather candidate block ids (>= Tb). #blocks == 96 barring exact
    // fp32 blockmax ties (measure-zero for continuous data); cap at BCAP.
    for (int i = tid; i < NBLKS; i += 256) {
        if (s_keys[i] >= Tb) {
            int p = atomicAdd(&s_nblk, 1);
            if (p < BCAP) s_blk[p] = i;
        }
    }
    __syncthreads();
    const int nblk = min(s_nblk, BCAP);
    const int ncand = nblk * 32;

    // ---- gather candidate elements (coalesced 128B per block)
    const float* sims = g_sims + (size_t)row * NC;
    for (int j = tid; j < ncand; j += 256) {
        int blk = s_blk[j >> 5];
        int idx = blk * 32 + (j & 31);
        float v = sims[idx];
        s_cv[j] = v;
        s_ci[j] = idx;
        s_ck[j] = f2k(v);
    }
    if (tid == 0) { s_cnt = 0; s_eqc = 0; }
    __syncthreads();

    // ---- exact top-96 among candidates
    int need_eq;
    unsigned T = radix_select(s_ck, ncand, CTXN, hist, psum, &s_bin, &s_need, tid, &need_eq);

    for (int j = tid; j < ncand; j += 256) {
        unsigned k = s_ck[j];
        if (k > T) {
            int p = atomicAdd(&s_cnt, 1);
            s_vals[p] = s_cv[j]; s_ids[p] = s_ci[j];
        } else if (k == T) {
            int q = atomicAdd(&s_eqc, 1);
            if (q < need_eq) {
                int p = atomicAdd(&s_cnt, 1);
                s_vals[p] = s_cv[j]; s_ids[p] = s_ci[j];
            }
        }
    }
    __syncthreads();

    // ---- softmax over 96
    if (tid == 0) {
        float m = -3.4e38f;
        for (int i = 0; i < CTXN; i++) m = fmaxf(m, s_vals[i]);
        s_red = m;
    }
    __syncthreads();
    float m = s_red;
    if (tid < CTXN) s_vals[tid] = expf(s_vals[tid] - m);
    __syncthreads();
    if (tid == 0) {
        float s = 0.f;
        for (int i = 0; i < CTXN; i++) s += s_vals[i];
        s_red = 1.f / s;
    }
    __syncthreads();
    if (tid < CTXN) {
        g_probs[row * CTXN + tid] = s_vals[tid] * s_red;
        g_tidx [row * CTXN + tid] = s_ids[tid];
    }
}

// ============================================================
// ctx GEMM1 (unchanged)
// ============================================================
__global__ void __launch_bounds__(256) ctx_mma1_kernel(
    const float* __restrict__ bt1)
{
    extern __shared__ __nv_bfloat16 sm[];
    __nv_bfloat16* sAh = sm;
    __nv_bfloat16* sAl = sAh + BM * ASTR;
    __nv_bfloat16* sBh = sAl + BM * ASTR;
    __nv_bfloat16* sBl = sBh + BM * ASTR;

    const int tid  = threadIdx.x;
    const int lane = tid & 31;
    const int w    = tid >> 5;
    const int wm   = w & 3;
    const int wn   = w >> 2;
    const int m0 = blockIdx.y * BM;
    const int n0 = blockIdx.x * BN;

    const uint32_t uAh = smem_u32(sAh), uAl = smem_u32(sAl);
    const uint32_t uBh = smem_u32(sBh), uBl = smem_u32(sBl);

    float c[2][8][4];
    #pragma unroll
    for (int i = 0; i < 2; i++)
        #pragma unroll
        for (int j = 0; j < 8; j++)
            #pragma unroll
            for (int q = 0; q < 4; q++) c[i][j][q] = 0.f;

    const int a_row = lane & 15, a_half = lane >> 4;
    const int b_grp = lane >> 3, b_row = lane & 7;
    const int b_nt = b_grp >> 1, b_kh = b_grp & 1;

    #pragma unroll 1
    for (int ch = 0; ch < 2; ch++) {
        const int kc = ch * BK;
        #pragma unroll
        for (int t = 0; t < 8; t++) {
            int idx = t * 256 + tid;
            int row = idx >> 4, q4 = (idx & 15) * 4;
            int p = m0 + row;
            int b = p / CTXN;
            int ci = g_tidx[p];
            float4 kv = *reinterpret_cast<const float4*>(&g_kb[(size_t)b * DM + kc + q4]);
            float4 cv = *reinterpret_cast<const float4*>(&g_cand_k[(size_t)ci * DM + kc + q4]);
            float d[4] = {kv.x - cv.x, kv.y - cv.y, kv.z - cv.z, kv.w - cv.w};
            __nv_bfloat16 hh[4], ll[4];
            #pragma unroll
            for (int e = 0; e < 4; e++) split_bf16(d[e], hh[e], ll[e]);
            *reinterpret_cast<ull*>(&sAh[row * ASTR + q4]) = *reinterpret_cast<ull*>(hh);
            *reinterpret_cast<ull*>(&sAl[row * ASTR + q4]) = *reinterpret_cast<ull*>(ll);
        }
        #pragma unroll
        for (int t = 0; t < 4; t++) {
            int idx = t * 256 + tid;
            int row = idx >> 3, c8 = (idx & 7) * 8;
            *reinterpret_cast<float4*>(&sBh[row * ASTR + c8]) =
                *reinterpret_cast<const float4*>(&g_wt1_hi[(n0 + row) * DM + kc + c8]);
            *reinterpret_cast<float4*>(&sBl[row * ASTR + c8]) =
                *reinterpret_cast<const float4*>(&g_wt1_lo[(n0 + row) * DM + kc + c8]);
        }
        __syncthreads();

        #pragma unroll
        for (int ks = 0; ks < BK / 16; ks++) {
            const int kb = ks * 16;
            uint32_t ah[2][4], al[2][4];
            #pragma unroll
            for (int mi = 0; mi < 2; mi++) {
                uint32_t off = (uint32_t)((wm * 32 + mi * 16 + a_row) * ASTR + kb + a_half * 8) * 2;
                ldsm4(ah[mi][0], ah[mi][1], ah[mi][2], ah[mi][3], uAh + off);
                ldsm4(al[mi][0], al[mi][1], al[mi][2], al[mi][3], uAl + off);
            }
            uint32_t bh[8][2], bl[8][2];
            #pragma unroll
            for (int nq = 0; nq < 4; nq++) {
                uint32_t off = (uint32_t)((wn * 64 + nq * 16 + b_nt * 8 + b_row) * ASTR + kb + b_kh * 8) * 2;
                uint32_t r0, r1, r2, r3;
                ldsm4(r0, r1, r2, r3, uBh + off);
                bh[nq * 2][0] = r0; bh[nq * 2][1] = r1;
                bh[nq * 2 + 1][0] = r2; bh[nq * 2 + 1][1] = r3;
                ldsm4(r0, r1, r2, r3, uBl + off);
                bl[nq * 2][0] = r0; bl[nq * 2][1] = r1;
                bl[nq * 2 + 1][0] = r2; bl[nq * 2 + 1][1] = r3;
            }
            #pragma unroll
            for (int mi = 0; mi < 2; mi++)
                #pragma unroll
                for (int ni = 0; ni < 8; ni++) {
                    mma16816(c[mi][ni], ah[mi][0], ah[mi][1], ah[mi][2], ah[mi][3], bh[ni][0], bh[ni][1]);
                    mma16816(c[mi][ni], ah[mi][0], ah[mi][1], ah[mi][2], ah[mi][3], bl[ni][0], bl[ni][1]);
                    mma16816(c[mi][ni], al[mi][0], al[mi][1], al[mi][2], al[mi][3], bh[ni][0], bh[ni][1]);
                }
        }
        __syncthreads();
    }

    const int col_base = n0 + wn * 64 + (lane & 3) * 2;
    #pragma unroll
    for (int mi = 0; mi < 2; mi++) {
        int row = m0 + wm * 32 + mi * 16 + (lane >> 2);
        #pragma unroll
        for (int ni = 0; ni < 8; ni++) {
            int col = col_base + ni * 8;
            float b0 = __ldg(&bt1[col]), b1v = __ldg(&bt1[col + 1]);
            float h00 = fmaxf(c[mi][ni][0] + b0, 0.f);
            float h01 = fmaxf(c[mi][ni][1] + b1v, 0.f);
            float h10 = fmaxf(c[mi][ni][2] + b0, 0.f);
            float h11 = fmaxf(c[mi][ni][3] + b1v, 0.f);
            __nv_bfloat16 h, l;
            __nv_bfloat162 ph, pl;
            split_bf16(h00, h, l); ph.x = h; pl.x = l;
            split_bf16(h01, h, l); ph.y = h; pl.y = l;
            *reinterpret_cast<__nv_bfloat162*>(&g_h_hi[(size_t)row * DB + col]) = ph;
            *reinterpret_cast<__nv_bfloat162*>(&g_h_lo[(size_t)row * DB + col]) = pl;
            split_bf16(h10, h, l); ph.x = h; pl.x = l;
            split_bf16(h11, h, l); ph.y = h; pl.y = l;
            *reinterpret_cast<__nv_bfloat162*>(&g_h_hi[(size_t)(row + 8) * DB + col]) = ph;
            *reinterpret_cast<__nv_bfloat162*>(&g_h_lo[(size_t)(row + 8) * DB + col]) = pl;
        }
    }
}

// ============================================================
// ctx GEMM2 (unchanged)
// ============================================================
__global__ void __launch_bounds__(256) ctx_mma2_kernel(
    const float* __restrict__ cand_y,
    const float* __restrict__ w_le, const float* __restrict__ b_le)
{
    extern __shared__ __nv_bfloat16 sm[];
    __nv_bfloat16* sAh = sm;
    __nv_bfloat16* sAl = sAh + BM * ASTR;
    __nv_bfloat16* sBh = sAl + BM * ASTR;
    __nv_bfloat16* sBl = sBh + BM * ASTR;

    const int tid  = threadIdx.x;
    const int lane = tid & 31;
    const int w    = tid >> 5;
    const int wm   = w & 3;
    const int wn   = w >> 2;
    const int m0 = blockIdx.y * BM;

    const uint32_t uAh = smem_u32(sAh), uAl = smem_u32(sAl);
    const uint32_t uBh = smem_u32(sBh), uBl = smem_u32(sBl);

    float c[2][8][4];
    #pragma unroll
    for (int i = 0; i < 2; i++)
        #pragma unroll
        for (int j = 0; j < 8; j++)
            #pragma unroll
            for (int q = 0; q < 4; q++) c[i][j][q] = 0.f;

    const int a_row = lane & 15, a_half = lane >> 4;
    const int b_grp = lane >> 3, b_row = lane & 7;
    const int b_nt = b_grp >> 1, b_kh = b_grp & 1;

    #pragma unroll 1
    for (int ch = 0; ch < 4; ch++) {
        const int kc = ch * BK;
        #pragma unroll
        for (int t = 0; t < 4; t++) {
            int idx = t * 256 + tid;
            int row = idx >> 3, c8 = (idx & 7) * 8;
            *reinterpret_cast<float4*>(&sAh[row * ASTR + c8]) =
                *reinterpret_cast<const float4*>(&g_h_hi[(size_t)(m0 + row) * DB + kc + c8]);
            *reinterpret_cast<float4*>(&sAl[row * ASTR + c8]) =
                *reinterpret_cast<const float4*>(&g_h_lo[(size_t)(m0 + row) * DB + kc + c8]);
        }
        #pragma unroll
        for (int t = 0; t < 4; t++) {
            int idx = t * 256 + tid;
            int row = idx >> 3, c8 = (idx & 7) * 8;
            *reinterpret_cast<float4*>(&sBh[row * ASTR + c8]) =
                *reinterpret_cast<const float4*>(&g_wt2_hi[row * DB + kc + c8]);
            *reinterpret_cast<float4*>(&sBl[row * ASTR + c8]) =
                *reinterpret_cast<const float4*>(&g_wt2_lo[row * DB + kc + c8]);
        }
        __syncthreads();

        #pragma unroll
        for (int ks = 0; ks < BK / 16; ks++) {
            const int kb = ks * 16;
            uint32_t ah[2][4], al[2][4];
            #pragma unroll
            for (int mi = 0; mi < 2; mi++) {
                uint32_t off = (uint32_t)((wm * 32 + mi * 16 + a_row) * ASTR + kb + a_half * 8) * 2;
                ldsm4(ah[mi][0], ah[mi][1], ah[mi][2], ah[mi][3], uAh + off);
                ldsm4(al[mi][0], al[mi][1], al[mi][2], al[mi][3], uAl + off);
            }
            uint32_t bh[8][2], bl[8][2];
            #pragma unroll
            for (int nq = 0; nq < 4; nq++) {
                uint32_t off = (uint32_t)((wn * 64 + nq * 16 + b_nt * 8 + b_row) * ASTR + kb + b_kh * 8) * 2;
                uint32_t r0, r1, r2, r3;
                ldsm4(r0, r1, r2, r3, uBh + off);
                bh[nq * 2][0] = r0; bh[nq * 2][1] = r1;
                bh[nq * 2 + 1][0] = r2; bh[nq * 2 + 1][1] = r3;
                ldsm4(r0, r1, r2, r3, uBl + off);
                bl[nq * 2][0] = r0; bl[nq * 2][1] = r1;
                bl[nq * 2 + 1][0] = r2; bl[nq * 2 + 1][1] = r3;
            }
            #pragma unroll
            for (int mi = 0; mi < 2; mi++)
                #pragma unroll
                for (int ni = 0; ni < 8; ni++) {
                    mma16816(c[mi][ni], ah[mi][0], ah[mi][1], ah[mi][2], ah[mi][3], bh[ni][0], bh[ni][1]);
                    mma16816(c[mi][ni], ah[mi][0], ah[mi][1], ah[mi][2], ah[mi][3], bl[ni][0], bl[ni][1]);
                    mma16816(c[mi][ni], al[mi][0], al[mi][1], al[mi][2], al[mi][3], bh[ni][0], bh[ni][1]);
                }
        }
        __syncthreads();
    }

    float* s_prob = reinterpret_cast<float*>(sm);
    float* s_y    = s_prob + BM;
    float* s_wle  = s_y + BM;
    float* s_ble  = s_wle + DM;
    if (tid < BM) {
        int p = m0 + tid;
        s_prob[tid] = g_probs[p];
        s_y[tid]    = __ldg(&cand_y[g_tidx[p]]);
    } else if (tid < BM + DM) {
        int j = tid - BM;
        s_wle[j] = __ldg(&w_le[j]);
        s_ble[j] = __ldg(&b_le[j]);
    }
    __syncthreads();

    const int col_base = wn * 64 + (lane & 3) * 2;
    #pragma unroll
    for (int mi = 0; mi < 2; mi++) {
        int r0 = wm * 32 + mi * 16 + (lane >> 2);
        int r1 = r0 + 8;
        float p0 = s_prob[r0], y0 = s_y[r0];
        float p1 = s_prob[r1], y1 = s_y[r1];
        #pragma unroll
        for (int ni = 0; ni < 8; ni++) {
            int col = col_base + ni * 8;
            float wl0 = s_wle[col], wl1 = s_wle[col + 1];
            float bl0 = s_ble[col], bl1 = s_ble[col + 1];
            *reinterpret_cast<float2*>(&g_vals[(size_t)(m0 + r0) * DM + col]) =
                make_float2(p0 * (y0 * wl0 + bl0 + c[mi][ni][0]),
                            p0 * (y0 * wl1 + bl1 + c[mi][ni][1]));
            *reinterpret_cast<float2*>(&g_vals[(size_t)(m0 + r1) * DM + col]) =
                make_float2(p1 * (y1 * wl0 + bl0 + c[mi][ni][2]),
                            p1 * (y1 * wl1 + bl1 + c[mi][ni][3]));
        }
    }
}

// Context reduce (unchanged)
__global__ void __launch_bounds__(128) ctx_reduce_kernel()
{
    const int b = blockIdx.x;
    const int j = threadIdx.x;
    const float* v = g_vals + (size_t)b * CTXN * DM + j;
    float s = 0.f;
    #pragma unroll 8
    for (int c = 0; c < CTXN; c++) s += v[(size_t)c * DM];
    g_ctx[(size_t)b * DM + j] = s;
}

// ============================================================
// Final (unchanged)
// ============================================================
__global__ void __launch_bounds__(128) final_kernel(
    const float* __restrict__ pg, const float* __restrict__ pb,
    const float* __restrict__ pW1, const float* __restrict__ pb1,
    const float* __restrict__ pW2, const float* __restrict__ pb2,
    const float* __restrict__ hg, const float* __restrict__ hb,
    const float* __restrict__ Wh, const float* __restrict__ bh,
    float* __restrict__ out)
{
    __shared__ float s_x[16][DM];
    __shared__ float s_ln[16][DM];
    __shared__ float s_h[16][DB];
    const int tid = threadIdx.x, lane = tid & 31, wid = tid >> 5;
    const int row0 = blockIdx.x * 16;

    #pragma unroll
    for (int r = 0; r < 16; r++)
        s_x[r][tid] = g_xb[(size_t)(row0 + r) * DM + tid]
                    + g_ctx[(size_t)(row0 + r) * DM + tid];
    __syncthreads();
    for (int r = wid; r < 16; r += 4) {
        float v0 = s_x[r][lane], v1 = s_x[r][lane + 32],
              v2 = s_x[r][lane + 64], v3 = s_x[r][lane + 96];
        float s = v0 + v1 + v2 + v3;
        #pragma unroll
        for (int o = 16; o; o >>= 1) s += __shfl_xor_sync(0xffffffffu, s, o);
        float mu = s * (1.f / 128.f);
        float d0 = v0 - mu, d1 = v1 - mu, d2 = v2 - mu, d3 = v3 - mu;
        float q = d0 * d0 + d1 * d1 + d2 * d2 + d3 * d3;
        #pragma unroll
        for (int o = 16; o; o >>= 1) q += __shfl_xor_sync(0xffffffffu, q, o);
        float rstd = rsqrtf(q * (1.f / 128.f) + 1e-5f);
        s_ln[r][lane]      = d0 * rstd * __ldg(&pg[lane])      + __ldg(&pb[lane]);
        s_ln[r][lane + 32] = d1 * rstd * __ldg(&pg[lane + 32]) + __ldg(&pb[lane + 32]);
        s_ln[r][lane + 64] = d2 * rstd * __ldg(&pg[lane + 64]) + __ldg(&pb[lane + 64]);
        s_ln[r][lane + 96] = d3 * rstd * __ldg(&pg[lane + 96]) + __ldg(&pb[lane + 96]);
    }
    __syncthreads();
    {
        ull a0[16], a1[16];
        float bb0 = __ldg(&pb1[tid]), bb1 = __ldg(&pb1[tid + 128]);
        #pragma unroll
        for (int r = 0; r < 16; r++) { a0[r] = pk(bb0, 0.f); a1[r] = pk(bb1, 0.f); }
        const ulonglong2* w40 = reinterpret_cast<const ulonglong2*>(pW1 + tid * DM);
        const ulonglong2* w41 = reinterpret_cast<const ulonglong2*>(pW1 + (tid + 128) * DM);
        #pragma unroll 4
        for (int jj = 0; jj < DM / 4; jj++) {
            ulonglong2 w0 = w40[jj], w1 = w41[jj];
            #pragma unroll
            for (int r = 0; r < 16; r++) {
                ulonglong2 s = *reinterpret_cast<const ulonglong2*>(&s_ln[r][jj * 4]);
                fma2(a0[r], w0.x, s.x); fma2(a0[r], w0.y, s.y);
                fma2(a1[r], w1.x, s.x); fma2(a1[r], w1.y, s.y);
            }
        }
        #pragma unroll
        for (int r = 0; r < 16; r++) {
            s_h[r][tid]       = fmaxf(fsum2(a0[r]), 0.f);
            s_h[r][tid + 128] = fmaxf(fsum2(a1[r]), 0.f);
        }
    }
    __syncthreads();
    {
        ull acc[16];
        float b2v = __ldg(&pb2[tid]);
        #pragma unroll
        for (int r = 0; r < 16; r++) acc[r] = pk(b2v, 0.f);
        const ulonglong2* w4 = reinterpret_cast<const ulonglong2*>(pW2 + tid * DB);
        #pragma unroll 2
        for (int jj = 0; jj < DB / 4; jj++) {
            ulonglong2 w = w4[jj];
            #pragma unroll
            for (int r = 0; r < 16; r++) {
                ulonglong2 s = *reinterpret_cast<const ulonglong2*>(&s_h[r][jj * 4]);
                fma2(acc[r], w.x, s.x); fma2(acc[r], w.y, s.y);
            }
        }
        #pragma unroll
        for (int r = 0; r < 16; r++) s_x[r][tid] += fsum2(acc[r]);
    }
    __syncthreads();
    for (int r = wid; r < 16; r += 4) {
        float v0 = s_x[r][lane], v1 = s_x[r][lane + 32],
              v2 = s_x[r][lane + 64], v3 = s_x[r][lane + 96];
        float s = v0 + v1 + v2 + v3;
        #pragma unroll
        for (int o = 16; o; o >>= 1) s += __shfl_xor_sync(0xffffffffu, s, o);
        float mu = s * (1.f / 128.f);
        float d0 = v0 - mu, d1 = v1 - mu, d2 = v2 - mu, d3 = v3 - mu;
        float q = d0 * d0 + d1 * d1 + d2 * d2 + d3 * d3;
        #pragma unroll
        for (int o = 16; o; o >>= 1) q += __shfl_xor_sync(0xffffffffu, q, o);
        float rstd = rsqrtf(q * (1.f / 128.f) + 1e-5f);
        s_ln[r][lane]      = fmaxf(d0 * rstd * __ldg(&hg[lane])      + __ldg(&hb[lane]), 0.f);
        s_ln[r][lane + 32] = fmaxf(d1 * rstd * __ldg(&hg[lane + 32]) + __ldg(&hb[lane + 32]), 0.f);
        s_ln[r][lane + 64] = fmaxf(d2 * rstd * __ldg(&hg[lane + 64]) + __ldg(&hb[lane + 64]), 0.f);
        s_ln[r][lane + 96] = fmaxf(d3 * rstd * __ldg(&hg[lane + 96]) + __ldg(&hb[lane + 96]), 0.f);
    }
    __syncthreads();
    for (int r = wid; r < 16; r += 4) {
        float p0 = 0.f, p1 = 0.f;
        #pragma unroll
        for (int q = 0; q < 4; q++) {
            float v = s_ln[r][lane + 32 * q];
            p0 += v * __ldg(&Wh[lane + 32 * q]);
            p1 += v * __ldg(&Wh[128 + lane + 32 * q]);
        }
        #pragma unroll
        for (int o = 16; o; o >>= 1) {
            p0 += __shfl_xor_sync(0xffffffffu, p0, o);
            p1 += __shfl_xor_sync(0xffffffffu, p1, o);
        }
        if (lane == 0) {
            out[(row0 + r) * 2 + 0] = p0 + __ldg(&bh[0]);
            out[(row0 + r) * 2 + 1] = p1 + __ldg(&bh[1]);
        }
    }
}

// ============================================================
extern "C" void kernel_launch(void* const* d_in, const int* in_sizes, int n_in,
                              void* d_out, int out_size)
{
    const float* x_num  = (const float*)d_in[0];
    const float* cand_x = (const float*)d_in[1];
    const float* cand_y = (const float*)d_in[2];
    const float* W_in   = (const float*)d_in[3];
    const float* b_in   = (const float*)d_in[4];
    const float* eW1    = (const float*)d_in[5];
    const float* eb1    = (const float*)d_in[6];
    const float* eW2    = (const float*)d_in[7];
    const float* eb2    = (const float*)d_in[8];
    const float* mg     = (const float*)d_in[9];
    const float* mb     = (const float*)d_in[10];
    const float* Wk     = (const float*)d_in[11];
    const float* bk     = (const float*)d_in[12];
    const float* w_le   = (const float*)d_in[13];
    const float* b_le   = (const float*)d_in[14];
    const float* Wt1    = (const float*)d_in[15];
    const float* bt1    = (const float*)d_in[16];
    const float* Wt2    = (const float*)d_in[17];
    const float* pg     = (const float*)d_in[18];
    const float* pb     = (const float*)d_in[19];
    const float* pW1    = (const float*)d_in[20];
    const float* pb1    = (const float*)d_in[21];
    const float* pW2    = (const float*)d_in[22];
    const float* pb2    = (const float*)d_in[23];
    const float* hg     = (const float*)d_in[24];
    const float* hb     = (const float*)d_in[25];
    const float* Wh     = (const float*)d_in[26];
    const float* bh     = (const float*)d_in[27];
    float* out = (float*)d_out;

    cudaFuncSetAttribute(encode_tc_kernel,
                         cudaFuncAttributeMaxDynamicSharedMemorySize, ENC_SMEM);
    cudaFuncSetAttribute(sims_mma_kernel,
                         cudaFuncAttributeMaxDynamicSharedMemorySize, SIMS_SMEM);
    cudaFuncSetAttribute(topk_kernel,
                         cudaFuncAttributeMaxDynamicSharedMemorySize, TOPK_SMEM);
    cudaFuncSetAttribute(ctx_mma1_kernel,
                         cudaFuncAttributeMaxDynamicSharedMemorySize, SIMS_SMEM);
    cudaFuncSetAttribute(ctx_mma2_kernel,
                         cudaFuncAttributeMaxDynamicSharedMemorySize, SIMS_SMEM);

    prep_kernel<<<(DB * DM + 255) / 256, 256>>>(Wt1, Wt2, W_in, eW1, eW2, Wk);
    encode_tc_kernel<<<ENC_GRID, 256, ENC_SMEM>>>(cand_x, x_num,
        b_in, eb1, eb2, mg, mb, bk);
    sims_mma_kernel<<<dim3(NTILES, NBATCH / BM), 256, SIMS_SMEM>>>();
    topk_kernel<<<NBATCH, 256, TOPK_SMEM>>>();
    ctx_mma1_kernel<<<dim3(DB / BN, NP / BM), 256, SIMS_SMEM>>>(bt1);
    ctx_mma2_kernel<<<dim3(1, NP / BM), 256, SIMS_SMEM>>>(cand_y, w_le, b_le);
    ctx_reduce_kernel<<<NBATCH, 128>>>();
    final_kernel<<<NBATCH / 16, 128>>>(pg, pb, pW1, pb1, pW2, pb2, hg, hb, Wh, bh, out);
}